// round 13
// baseline (speedup 1.0000x reference)
#include <cuda_runtime.h>
#include <cuda_bf16.h>
#include <cuda_fp16.h>

// Problem constants
#define BB 2
#define LL 1024
#define CA 512
#define CS 384
#define CZ 64
#define HH 16
#define DD 32
#define MM (BB*LL)          // 2048 rows
#define SCALE 0.17677669529663687f  // 1/sqrt(32)

typedef unsigned long long U64;
__device__ __forceinline__ U64 pk2(float lo, float hi){ U64 r; asm("mov.b64 %0, {%1,%2};":"=l"(r):"f"(lo),"f"(hi)); return r; }
__device__ __forceinline__ void fma2(U64 &d, U64 a, U64 b){ asm("fma.rn.f32x2 %0, %1, %2, %3;":"=l"(d):"l"(a),"l"(b),"l"(d)); }
__device__ __forceinline__ float2 up2(U64 v){ float2 r; asm("mov.b64 {%0,%1}, %2;":"=f"(r.x),"=f"(r.y):"l"(v)); return r; }

// -------------------- device scratch --------------------
__device__ __align__(16) float g_s_ln[MM*CS];
__device__ __align__(16) float g_a_ln[MM*CA];
__device__ __align__(16) float g_anorm[MM*CA];
__device__ __align__(16) float g_glast[MM*CA];
__device__ __align__(16) float g_q[MM*CA];   // [b][h][l][d]
__device__ __align__(16) float g_k[MM*CA];
__device__ __align__(16) float g_v[MM*CA];
__device__ __align__(16) float g_g[MM*CA];   // pre-sigmoid gate
__device__ __align__(16) float g_ao[MM*CA];  // attention out (0-init; inactive rows stay 0)
__device__ __align__(16) __half g_biash[(size_t)BB*HH*LL*LL]; // 67MB fp16 bias
__device__ int g_qidx[BB*LL];
__device__ int g_qcnt[BB];

__device__ __forceinline__ float sigm(float x){ return 1.f/(1.f+__expf(-x)); }

// -------------------- kernel 0: build compacted active-q index list --------------
__global__ __launch_bounds__(1024) void build_idx_kernel(const int* __restrict__ mask)
{
    int b = blockIdx.x;
    int tid = threadIdx.x;          // 0..1023
    int lane = tid & 31, wid = tid >> 5;
    __shared__ unsigned wm[32];
    __shared__ int wpre[32];
    bool act = (mask[b*LL + tid] != 0);
    unsigned bal = __ballot_sync(0xffffffffu, act);
    if(lane == 0) wm[wid] = bal;
    __syncthreads();
    if(tid == 0){
        int s = 0;
        for(int i=0;i<32;i++){ wpre[i] = s; s += __popc(wm[i]); }
        g_qcnt[b] = s;
    }
    __syncthreads();
    if(act){
        unsigned below = bal & ((lane == 0) ? 0u : (0xffffffffu >> (32-lane)));
        int rank = wpre[wid] + __popc(below);
        g_qidx[b*LL + rank] = tid;
    }
}

// -------------------- kernel 1: row layernorms --------------------
__global__ __launch_bounds__(256) void ln_kernel(
    const float* __restrict__ a, const float* __restrict__ s,
    const float* __restrict__ s_scale)
{
    int row = blockIdx.x;
    int tid = threadIdx.x;
    __shared__ float rs[16];
    const float* ar = a + (size_t)row*CA;
    float x0 = ar[tid], x1 = ar[tid+256];
    float sum = x0+x1, ss = x0*x0 + x1*x1;
    #pragma unroll
    for(int o=16;o;o>>=1){ sum += __shfl_xor_sync(0xffffffffu,sum,o); ss += __shfl_xor_sync(0xffffffffu,ss,o); }
    if((tid&31)==0){ rs[tid>>5]=sum; rs[8+(tid>>5)]=ss; }
    __syncthreads();
    if(tid==0){ float S=0,Q=0; for(int i=0;i<8;i++){S+=rs[i];Q+=rs[8+i];} rs[0]=S; rs[8]=Q; }
    __syncthreads();
    float mean = rs[0]*(1.f/CA);
    float var  = rs[8]*(1.f/CA) - mean*mean;
    float rstd = rsqrtf(var + 1e-5f);
    g_a_ln[(size_t)row*CA + tid]      = (x0-mean)*rstd;
    g_a_ln[(size_t)row*CA + tid+256]  = (x1-mean)*rstd;
    __syncthreads();
    const float* sr = s + (size_t)row*CS;
    float y0 = sr[tid];
    float y1 = (tid < CS-256) ? sr[tid+256] : 0.f;
    sum = y0+y1; ss = y0*y0 + y1*y1;
    #pragma unroll
    for(int o=16;o;o>>=1){ sum += __shfl_xor_sync(0xffffffffu,sum,o); ss += __shfl_xor_sync(0xffffffffu,ss,o); }
    if((tid&31)==0){ rs[tid>>5]=sum; rs[8+(tid>>5)]=ss; }
    __syncthreads();
    if(tid==0){ float S=0,Q=0; for(int i=0;i<8;i++){S+=rs[i];Q+=rs[8+i];} rs[0]=S; rs[8]=Q; }
    __syncthreads();
    mean = rs[0]*(1.f/CS);
    var  = rs[8]*(1.f/CS) - mean*mean;
    rstd = rsqrtf(var + 1e-5f);
    g_s_ln[(size_t)row*CS + tid] = (y0-mean)*rstd*s_scale[tid];
    if(tid < CS-256)
        g_s_ln[(size_t)row*CS + tid+256] = (y1-mean)*rstd*s_scale[tid+256];
}

// -------------------- kernel 2: a_norm + glast (triple GEMM, f32x2) --------------------
__global__ __launch_bounds__(256) void anorm_kernel(
    const float* __restrict__ s_raw,
    const float* __restrict__ ada_w_s, const float* __restrict__ ada_b_s,
    const float* __restrict__ ada_w_nb,
    const float* __restrict__ w_last, const float* __restrict__ b_last)
{
    const int K = CS;
    __shared__ __align__(16) float As1[16][72];
    __shared__ __align__(16) float As2[16][72];
    __shared__ __align__(16) float Bs1[16][72];
    __shared__ __align__(16) float Bs2[16][72];
    __shared__ __align__(16) float Bs3[16][72];
    int tid = threadIdx.x;
    int tx = tid & 15, ty = tid >> 4;
    int m0 = blockIdx.y*64, n0 = blockIdx.x*64;
    U64 c1[4][2]={}, c2[4][2]={}, c3[4][2]={};
    for(int k0=0;k0<K;k0+=16){
        #pragma unroll
        for(int p=0;p<4;p++){
            int e = p*256 + tid;
            int mm = e>>4, kk = e&15;
            As1[kk][mm] = g_s_ln[(size_t)(m0+mm)*K + k0+kk];
            As2[kk][mm] = s_raw[(size_t)(m0+mm)*K + k0+kk];
            Bs1[kk][mm] = ada_w_s [(size_t)(n0+mm)*K + k0+kk];
            Bs2[kk][mm] = ada_w_nb[(size_t)(n0+mm)*K + k0+kk];
            Bs3[kk][mm] = w_last  [(size_t)(n0+mm)*K + k0+kk];
        }
        __syncthreads();
        #pragma unroll
        for(int kk=0;kk<16;kk++){
            float4 a1 = *(const float4*)&As1[kk][ty*4];
            float4 a2 = *(const float4*)&As2[kk][ty*4];
            ulonglong2 b1 = *(const ulonglong2*)&Bs1[kk][tx*4];
            ulonglong2 b2 = *(const ulonglong2*)&Bs2[kk][tx*4];
            ulonglong2 b3 = *(const ulonglong2*)&Bs3[kk][tx*4];
            U64 a1d[4], a2d[4];
            a1d[0]=pk2(a1.x,a1.x); a1d[1]=pk2(a1.y,a1.y); a1d[2]=pk2(a1.z,a1.z); a1d[3]=pk2(a1.w,a1.w);
            a2d[0]=pk2(a2.x,a2.x); a2d[1]=pk2(a2.y,a2.y); a2d[2]=pk2(a2.z,a2.z); a2d[3]=pk2(a2.w,a2.w);
            #pragma unroll
            for(int i=0;i<4;i++){
                fma2(c1[i][0],a1d[i],b1.x); fma2(c1[i][1],a1d[i],b1.y);
                fma2(c2[i][0],a1d[i],b2.x); fma2(c2[i][1],a1d[i],b2.y);
                fma2(c3[i][0],a2d[i],b3.x); fma2(c3[i][1],a2d[i],b3.y);
            }
        }
        __syncthreads();
    }
    #pragma unroll
    for(int i=0;i<4;i++){
        int m = m0 + ty*4 + i;
        #pragma unroll
        for(int jp=0;jp<2;jp++){
            float2 v1 = up2(c1[i][jp]), v2 = up2(c2[i][jp]), v3 = up2(c3[i][jp]);
            int n = n0 + tx*4 + jp*2;
            float sgA = sigm(v1.x + ada_b_s[n]);
            float sgB = sigm(v1.y + ada_b_s[n+1]);
            g_anorm[(size_t)m*CA + n]   = sgA * g_a_ln[(size_t)m*CA + n]   + v2.x;
            g_anorm[(size_t)m*CA + n+1] = sgB * g_a_ln[(size_t)m*CA + n+1] + v2.y;
            g_glast[(size_t)m*CA + n]   = sigm(v3.x + b_last[n]);
            g_glast[(size_t)m*CA + n+1] = sigm(v3.y + b_last[n+1]);
        }
    }
}

// -------------------- kernel 3: QKVG projections (f32x2, double-buffered) ----------
__global__ __launch_bounds__(256) void qkvg_kernel(
    const float* __restrict__ wq, const float* __restrict__ bq,
    const float* __restrict__ wk, const float* __restrict__ bk,
    const float* __restrict__ wv, const float* __restrict__ bv,
    const float* __restrict__ wg, const float* __restrict__ bg)
{
    const int K = CA;
    __shared__ __align__(16) float As[2][16][136];
    __shared__ __align__(16) float Bs[2][16][136];
    int tid = threadIdx.x;
    int tx = tid & 15, ty = tid >> 4;
    int m0 = blockIdx.y*128;
    int n0 = blockIdx.x*128;
    int which = n0 >> 9;
    int nn0 = n0 & 511;
    const float* W  = (which==0)?wq : (which==1)?wk : (which==2)?wv : wg;
    const float* Bv = (which==0)?bq : (which==1)?bk : (which==2)?bv : bg;
    U64 c[8][4]={};

    float pa[8], pb[8];
    int mmv[8], kkv[8];
    #pragma unroll
    for(int p=0;p<8;p++){ int e = p*256 + tid; mmv[p]=e>>4; kkv[p]=e&15; }

    #pragma unroll
    for(int p=0;p<8;p++){
        pa[p] = g_anorm[(size_t)(m0+mmv[p])*K + kkv[p]];
        pb[p] = W[(size_t)(nn0+mmv[p])*K + kkv[p]];
    }
    #pragma unroll
    for(int p=0;p<8;p++){ As[0][kkv[p]][mmv[p]]=pa[p]; Bs[0][kkv[p]][mmv[p]]=pb[p]; }
    __syncthreads();

    int buf = 0;
    for(int t=0;t<K/16;t++){
        if(t < K/16-1){
            int k0 = (t+1)*16;
            #pragma unroll
            for(int p=0;p<8;p++){
                pa[p] = g_anorm[(size_t)(m0+mmv[p])*K + k0+kkv[p]];
                pb[p] = W[(size_t)(nn0+mmv[p])*K + k0+kkv[p]];
            }
        }
        #pragma unroll
        for(int kk=0;kk<16;kk++){
            float4 t0 = *(const float4*)&As[buf][kk][ty*8];
            float4 t1 = *(const float4*)&As[buf][kk][ty*8+4];
            ulonglong2 b0 = *(const ulonglong2*)&Bs[buf][kk][tx*8];
            ulonglong2 b1 = *(const ulonglong2*)&Bs[buf][kk][tx*8+4];
            U64 ad[8];
            ad[0]=pk2(t0.x,t0.x); ad[1]=pk2(t0.y,t0.y); ad[2]=pk2(t0.z,t0.z); ad[3]=pk2(t0.w,t0.w);
            ad[4]=pk2(t1.x,t1.x); ad[5]=pk2(t1.y,t1.y); ad[6]=pk2(t1.z,t1.z); ad[7]=pk2(t1.w,t1.w);
            #pragma unroll
            for(int i=0;i<8;i++){
                fma2(c[i][0],ad[i],b0.x); fma2(c[i][1],ad[i],b0.y);
                fma2(c[i][2],ad[i],b1.x); fma2(c[i][3],ad[i],b1.y);
            }
        }
        if(t < K/16-1){
            #pragma unroll
            for(int p=0;p<8;p++){ As[buf^1][kkv[p]][mmv[p]]=pa[p]; Bs[buf^1][kkv[p]][mmv[p]]=pb[p]; }
            __syncthreads();
            buf ^= 1;
        }
    }

    float* dst = (which==0)?g_q : (which==1)?g_k : g_v;
    #pragma unroll
    for(int i=0;i<8;i++){
        int m = m0 + ty*8 + i;
        #pragma unroll
        for(int jp=0;jp<4;jp++){
            float2 v = up2(c[i][jp]);
            #pragma unroll
            for(int l=0;l<2;l++){
                int nn = nn0 + tx*8 + jp*2 + l;
                float val = (l?v.y:v.x) + Bv[nn];
                if(which < 3){
                    int hh = nn>>5, dd2 = nn&31;
                    int bb = m>>10, ll = m&1023;
                    dst[(((size_t)(bb*HH+hh))*LL + ll)*DD + dd2] = val;
                } else {
                    g_g[(size_t)m*CA + nn] = val;
                }
            }
        }
    }
}

// -------------------- kernel 4: pair bias (mask-skip, no dead stores) ----------
__global__ __launch_bounds__(256) void bias_kernel(
    const float* __restrict__ z, const float* __restrict__ z_scale,
    const float* __restrict__ wz, const int* __restrict__ mask)
{
    __shared__ __align__(16) U64 wzs2[HH][CZ/2];
    __shared__ float wsum[HH];
    int tid = threadIdx.x;
    for(int e=tid;e<HH*(CZ/2);e+=256){
        int h = e>>5, c2 = e&31;
        float w0 = wz[h*CZ + 2*c2    ]*z_scale[2*c2    ];
        float w1 = wz[h*CZ + 2*c2 + 1]*z_scale[2*c2 + 1];
        wzs2[h][c2] = pk2(w0,w1);
    }
    __syncthreads();
    if(tid < HH){
        float S=0.f;
        for(int c2=0;c2<CZ/2;c2++){ float2 t=up2(wzs2[tid][c2]); S += t.x + t.y; }
        wsum[tid]=S;
    }
    __syncthreads();

    size_t t0 = (size_t)blockIdx.x*256 + tid;
    int b_ = (int)(t0>>20), q_ = (int)((t0>>10)&1023), k_ = (int)(t0&1023);

    bool active = (mask[b_*LL + q_] != 0) && (mask[b_*LL + k_] != 0);
    if(!active) return;

    size_t ob = (((size_t)(b_*HH))*LL + q_)*LL + k_;
    const float4* zp = (const float4*)(z + t0*CZ);
    U64 acc[HH];
    #pragma unroll
    for(int h=0;h<HH;h++) acc[h]=0ull;
    U64 sum=0ull, ssq=0ull;
    const U64 one2 = pk2(1.f,1.f);

    #pragma unroll
    for(int cs=0;cs<16;cs++){
        float4 a = zp[cs];
        U64 p01 = pk2(a.x,a.y);
        U64 p23 = pk2(a.z,a.w);
        fma2(sum,p01,one2); fma2(sum,p23,one2);
        fma2(ssq,p01,p01);  fma2(ssq,p23,p23);
        #pragma unroll
        for(int h=0;h<HH;h++){
            ulonglong2 w = *(const ulonglong2*)&wzs2[h][cs*2];
            fma2(acc[h],p01,w.x);
            fma2(acc[h],p23,w.y);
        }
    }
    float2 s2=up2(sum), q2=up2(ssq);
    float mean = (s2.x+s2.y)*(1.f/CZ);
    float var  = (q2.x+q2.y)*(1.f/CZ) - mean*mean;
    float rstd = rsqrtf(var + 1e-5f);

    #pragma unroll
    for(int h=0;h<HH;h++){
        float2 d = up2(acc[h]);
        float v = rstd*((d.x+d.y) - mean*wsum[h]);
        g_biash[ob + (size_t)h*LL*LL] = __float2half(v);
    }
}

// -------------------- kernel 5: attention (compacted rows, 2 threads/row) --------
__global__ __launch_bounds__(128) void attn_kernel(const int* __restrict__ mask)
{
    __shared__ __align__(16) float Ks[64*32];
    __shared__ __align__(16) float Vs[64*32];
    __shared__ __align__(16) __half bsh[64][80];
    __shared__ float mk[64];
    __shared__ int sQ[64];

    int tid = threadIdx.x;          // 128
    int b = blockIdx.z, h = blockIdx.y;
    int cnt = g_qcnt[b];
    int base = blockIdx.x*64;
    if(base >= cnt) return;         // uniform per block

    if(tid < 64){
        int slot = base + tid;
        sQ[tid] = g_qidx[b*LL + (slot < cnt ? slot : cnt-1)];
    }
    __syncthreads();

    int row = tid >> 1;             // compacted slot within block
    int half = tid & 1;
    bool act = (base + row) < cnt;
    int q = sQ[row];

    const float* qp = g_q + (((size_t)(b*HH+h))*LL + q)*DD + half*16;
    U64 qr2[8];
    #pragma unroll
    for(int i=0;i<4;i++){
        float4 t4 = ((const float4*)qp)[i];
        qr2[i*2]   = pk2(t4.x*SCALE, t4.y*SCALE);
        qr2[i*2+1] = pk2(t4.z*SCALE, t4.w*SCALE);
    }
    U64 O2[8];
    #pragma unroll
    for(int i=0;i<8;i++) O2[i]=0ull;
    float lrun = 0.f;

    const float* Kbase = g_k + ((size_t)(b*HH+h))*LL*DD;
    const float* Vbase = g_v + ((size_t)(b*HH+h))*LL*DD;
    const __half* bbase = g_biash + ((size_t)(b*HH+h))*LL*LL;   // + q*LL per row

    for(int kt=0; kt<LL; kt+=64){
        __syncthreads();
        #pragma unroll
        for(int p=0;p<4;p++){
            int f = p*128 + tid;  // 512 float4s
            ((float4*)Ks)[f] = ((const float4*)(Kbase + (size_t)kt*DD))[f];
            ((float4*)Vs)[f] = ((const float4*)(Vbase + (size_t)kt*DD))[f];
        }
        #pragma unroll
        for(int p=0;p<4;p++){
            int c = p*128 + tid;   // 512 chunks of 8 halves
            int r = c>>3, part = c&7;
            *(float4*)&bsh[r][part*8] = ((const float4*)(bbase + (size_t)sQ[r]*LL + kt))[part];
        }
        if(tid < 64) mk[tid] = mask[b*LL + kt + tid] ? 0.f : -1.f;
        __syncthreads();

        for(int j0=0;j0<64;j0+=4){
            const __half2* bp = (const __half2*)&bsh[row][j0];
            float2 b01 = __half22float2(bp[0]);
            float2 b23 = __half22float2(bp[1]);
            float bb4[4] = {b01.x, b01.y, b23.x, b23.y};
            #pragma unroll
            for(int jj=0;jj<4;jj++){
                int j = j0 + jj;
                if(mk[j] == 0.f){   // uniform across block: skip masked keys
                    const ulonglong2* kp = (const ulonglong2*)&Ks[j*32 + half*16];
                    U64 sacc = 0ull;
                    #pragma unroll
                    for(int i=0;i<4;i++){
                        ulonglong2 kv = kp[i];
                        fma2(sacc, qr2[i*2],   kv.x);
                        fma2(sacc, qr2[i*2+1], kv.y);
                    }
                    float2 sp = up2(sacc);
                    float part = sp.x + sp.y;
                    float tot = part + __shfl_xor_sync(0xffffffffu, part, 1);
                    float s_ = tot + bb4[jj];
                    float p_ = __expf(s_);
                    lrun += p_;
                    U64 pp = pk2(p_, p_);
                    const ulonglong2* vp = (const ulonglong2*)&Vs[j*32 + half*16];
                    #pragma unroll
                    for(int i=0;i<4;i++){
                        ulonglong2 vv = vp[i];
                        fma2(O2[i*2],   pp, vv.x);
                        fma2(O2[i*2+1], pp, vv.y);
                    }
                }
            }
        }
    }
    if(act){
        float inv = 1.f/fmaxf(lrun, 1e-20f);
        float* dst = g_ao + ((size_t)(b*LL + q))*CA + h*DD + half*16;
        #pragma unroll
        for(int i=0;i<4;i++){
            float2 v0 = up2(O2[i*2]), v1 = up2(O2[i*2+1]);
            ((float4*)dst)[i] = make_float4(v0.x*inv, v0.y*inv, v1.x*inv, v1.y*inv);
        }
    }
}

// -------------------- kernel 6: output GEMM (f32x2) --------------------
__global__ __launch_bounds__(256) void out_kernel(
    const float* __restrict__ wo, const float* __restrict__ bo,
    const int* __restrict__ mask, float* __restrict__ out)
{
    const int K = CA;
    __shared__ __align__(16) float As[16][72];
    __shared__ __align__(16) float Bs[16][72];
    int tid = threadIdx.x;
    int tx = tid & 15, ty = tid >> 4;
    int m0 = blockIdx.y*64, n0 = blockIdx.x*64;
    U64 c[4][2]={};
    for(int k0=0;k0<K;k0+=16){
        #pragma unroll
        for(int p=0;p<4;p++){
            int e = p*256 + tid;
            int mm = e>>4, kk = e&15;
            size_t ai = (size_t)(m0+mm)*K + k0+kk;
            As[kk][mm] = sigm(g_g[ai]) * g_ao[ai];
            Bs[kk][mm] = wo[(size_t)(n0+mm)*K + k0+kk];
        }
        __syncthreads();
        #pragma unroll
        for(int kk=0;kk<16;kk++){
            float4 a4 = *(const float4*)&As[kk][ty*4];
            ulonglong2 bu = *(const ulonglong2*)&Bs[kk][tx*4];
            U64 ad[4];
            ad[0]=pk2(a4.x,a4.x); ad[1]=pk2(a4.y,a4.y); ad[2]=pk2(a4.z,a4.z); ad[3]=pk2(a4.w,a4.w);
            #pragma unroll
            for(int i=0;i<4;i++){
                fma2(c[i][0],ad[i],bu.x);
                fma2(c[i][1],ad[i],bu.y);
            }
        }
        __syncthreads();
    }
    #pragma unroll
    for(int i=0;i<4;i++){
        int m = m0 + ty*4 + i;
        float mq = mask[m] ? 1.f : 0.f;
        #pragma unroll
        for(int jp=0;jp<2;jp++){
            float2 v = up2(c[i][jp]);
            int n = n0 + tx*4 + jp*2;
            out[(size_t)m*CA + n]   = (v.x + bo[n])   * g_glast[(size_t)m*CA + n]   * mq;
            out[(size_t)m*CA + n+1] = (v.y + bo[n+1]) * g_glast[(size_t)m*CA + n+1] * mq;
        }
    }
}

// -------------------- launch (fork-join: bias branch overlaps main chain) ----------
extern "C" void kernel_launch(void* const* d_in, const int* in_sizes, int n_in,
                              void* d_out, int out_size)
{
    const float* a          = (const float*)d_in[0];
    const float* s          = (const float*)d_in[1];
    const float* z          = (const float*)d_in[2];
    const float* ln_s_scale = (const float*)d_in[3];
    const float* ada_w_s    = (const float*)d_in[4];
    const float* ada_b_s    = (const float*)d_in[5];
    const float* ada_w_nb   = (const float*)d_in[6];
    const float* wq = (const float*)d_in[7];  const float* bq = (const float*)d_in[8];
    const float* wk = (const float*)d_in[9];  const float* bk = (const float*)d_in[10];
    const float* wv = (const float*)d_in[11]; const float* bv = (const float*)d_in[12];
    const float* wg = (const float*)d_in[13]; const float* bg = (const float*)d_in[14];
    const float* wo = (const float*)d_in[15]; const float* bo = (const float*)d_in[16];
    const float* ln_z_scale = (const float*)d_in[17];
    const float* wz         = (const float*)d_in[18];
    const float* w_last     = (const float*)d_in[19];
    const float* b_last     = (const float*)d_in[20];
    const int*   mask       = (const int*)d_in[21];
    float* out = (float*)d_out;

    static cudaStream_t s_bias = 0;
    static cudaEvent_t ev_fork = 0, ev_join = 0;
    if(!s_bias){
        cudaStreamCreateWithFlags(&s_bias, cudaStreamNonBlocking);
        cudaEventCreateWithFlags(&ev_fork, cudaEventDisableTiming);
        cudaEventCreateWithFlags(&ev_join, cudaEventDisableTiming);
    }

    // fork: bias branch (depends only on z, ln_z_scale, wz, mask)
    cudaEventRecord(ev_fork, 0);
    cudaStreamWaitEvent(s_bias, ev_fork, 0);
    build_idx_kernel<<<BB, 1024, 0, s_bias>>>(mask);
    bias_kernel<<<(BB*LL*LL)/256, 256, 0, s_bias>>>(z, ln_z_scale, wz, mask);
    cudaEventRecord(ev_join, s_bias);

    // main branch
    ln_kernel<<<MM, 256>>>(a, s, ln_s_scale);
    anorm_kernel<<<dim3(CA/64, MM/64), 256>>>(s, ada_w_s, ada_b_s, ada_w_nb, w_last, b_last);
    qkvg_kernel<<<dim3(2048/128, MM/128), 256>>>(wq,bq, wk,bk, wv,bv, wg,bg);

    // join: attention needs bias + index list + q/k/v
    cudaStreamWaitEvent(0, ev_join, 0);
    attn_kernel<<<dim3(LL/64, HH, BB), 128>>>(mask);
    out_kernel<<<dim3(CA/64, MM/64), 256>>>(wo, bo, mask, out);
}

// round 14
// speedup vs baseline: 1.0302x; 1.0302x over previous
#include <cuda_runtime.h>
#include <cuda_bf16.h>
#include <cuda_fp16.h>

// Problem constants
#define BB 2
#define LL 1024
#define CA 512
#define CS 384
#define CZ 64
#define HH 16
#define DD 32
#define MM (BB*LL)          // 2048 rows
#define SCALE 0.17677669529663687f  // 1/sqrt(32)

typedef unsigned long long U64;
__device__ __forceinline__ U64 pk2(float lo, float hi){ U64 r; asm("mov.b64 %0, {%1,%2};":"=l"(r):"f"(lo),"f"(hi)); return r; }
__device__ __forceinline__ void fma2(U64 &d, U64 a, U64 b){ asm("fma.rn.f32x2 %0, %1, %2, %3;":"=l"(d):"l"(a),"l"(b),"l"(d)); }
__device__ __forceinline__ float2 up2(U64 v){ float2 r; asm("mov.b64 {%0,%1}, %2;":"=f"(r.x),"=f"(r.y):"l"(v)); return r; }

// -------------------- device scratch --------------------
__device__ __align__(16) float g_s_ln[MM*CS];
__device__ __align__(16) float g_a_ln[MM*CA];
__device__ __align__(16) float g_anorm[MM*CA];
__device__ __align__(16) float g_glast[MM*CA];
__device__ __align__(16) float g_q[MM*CA];   // [b][h][l][d]
__device__ __align__(16) float g_k[MM*CA];
__device__ __align__(16) float g_v[MM*CA];
__device__ __align__(16) float g_g[MM*CA];   // pre-sigmoid gate
__device__ __align__(16) float g_ao[MM*CA];  // attention out [b][l][h*32+d]
__device__ __align__(16) __half g_biash[(size_t)BB*HH*LL*LL]; // 67MB fp16 bias

__device__ __forceinline__ float sigm(float x){ return 1.f/(1.f+__expf(-x)); }

// -------------------- kernel 1: row layernorms --------------------
__global__ __launch_bounds__(256) void ln_kernel(
    const float* __restrict__ a, const float* __restrict__ s,
    const float* __restrict__ s_scale)
{
    int row = blockIdx.x;
    int tid = threadIdx.x;
    __shared__ float rs[16];
    const float* ar = a + (size_t)row*CA;
    float x0 = ar[tid], x1 = ar[tid+256];
    float sum = x0+x1, ss = x0*x0 + x1*x1;
    #pragma unroll
    for(int o=16;o;o>>=1){ sum += __shfl_xor_sync(0xffffffffu,sum,o); ss += __shfl_xor_sync(0xffffffffu,ss,o); }
    if((tid&31)==0){ rs[tid>>5]=sum; rs[8+(tid>>5)]=ss; }
    __syncthreads();
    if(tid==0){ float S=0,Q=0; for(int i=0;i<8;i++){S+=rs[i];Q+=rs[8+i];} rs[0]=S; rs[8]=Q; }
    __syncthreads();
    float mean = rs[0]*(1.f/CA);
    float var  = rs[8]*(1.f/CA) - mean*mean;
    float rstd = rsqrtf(var + 1e-5f);
    g_a_ln[(size_t)row*CA + tid]      = (x0-mean)*rstd;
    g_a_ln[(size_t)row*CA + tid+256]  = (x1-mean)*rstd;
    __syncthreads();
    const float* sr = s + (size_t)row*CS;
    float y0 = sr[tid];
    float y1 = (tid < CS-256) ? sr[tid+256] : 0.f;
    sum = y0+y1; ss = y0*y0 + y1*y1;
    #pragma unroll
    for(int o=16;o;o>>=1){ sum += __shfl_xor_sync(0xffffffffu,sum,o); ss += __shfl_xor_sync(0xffffffffu,ss,o); }
    if((tid&31)==0){ rs[tid>>5]=sum; rs[8+(tid>>5)]=ss; }
    __syncthreads();
    if(tid==0){ float S=0,Q=0; for(int i=0;i<8;i++){S+=rs[i];Q+=rs[8+i];} rs[0]=S; rs[8]=Q; }
    __syncthreads();
    mean = rs[0]*(1.f/CS);
    var  = rs[8]*(1.f/CS) - mean*mean;
    rstd = rsqrtf(var + 1e-5f);
    g_s_ln[(size_t)row*CS + tid] = (y0-mean)*rstd*s_scale[tid];
    if(tid < CS-256)
        g_s_ln[(size_t)row*CS + tid+256] = (y1-mean)*rstd*s_scale[tid+256];
}

// -------------------- kernel 2: a_norm + glast (triple GEMM, f32x2, double-buffered) ----
__global__ __launch_bounds__(256) void anorm_kernel(
    const float* __restrict__ s_raw,
    const float* __restrict__ ada_w_s, const float* __restrict__ ada_b_s,
    const float* __restrict__ ada_w_nb,
    const float* __restrict__ w_last, const float* __restrict__ b_last)
{
    const int K = CS;
    __shared__ __align__(16) float As1[2][16][72];
    __shared__ __align__(16) float As2[2][16][72];
    __shared__ __align__(16) float Bs1[2][16][72];
    __shared__ __align__(16) float Bs2[2][16][72];
    __shared__ __align__(16) float Bs3[2][16][72];
    int tid = threadIdx.x;
    int tx = tid & 15, ty = tid >> 4;
    int m0 = blockIdx.y*64, n0 = blockIdx.x*64;
    U64 c1[4][2]={}, c2[4][2]={}, c3[4][2]={};

    int mmv[4], kkv[4];
    #pragma unroll
    for(int p=0;p<4;p++){ int e = p*256 + tid; mmv[p]=e>>4; kkv[p]=e&15; }
    float p1[4],p2[4],p3[4],p4[4],p5[4];

    #pragma unroll
    for(int p=0;p<4;p++){
        p1[p] = g_s_ln[(size_t)(m0+mmv[p])*K + kkv[p]];
        p2[p] = s_raw [(size_t)(m0+mmv[p])*K + kkv[p]];
        p3[p] = ada_w_s [(size_t)(n0+mmv[p])*K + kkv[p]];
        p4[p] = ada_w_nb[(size_t)(n0+mmv[p])*K + kkv[p]];
        p5[p] = w_last  [(size_t)(n0+mmv[p])*K + kkv[p]];
    }
    #pragma unroll
    for(int p=0;p<4;p++){
        As1[0][kkv[p]][mmv[p]]=p1[p]; As2[0][kkv[p]][mmv[p]]=p2[p];
        Bs1[0][kkv[p]][mmv[p]]=p3[p]; Bs2[0][kkv[p]][mmv[p]]=p4[p]; Bs3[0][kkv[p]][mmv[p]]=p5[p];
    }
    __syncthreads();

    int buf = 0;
    for(int t=0;t<K/16;t++){
        if(t < K/16-1){
            int k0 = (t+1)*16;
            #pragma unroll
            for(int p=0;p<4;p++){
                p1[p] = g_s_ln[(size_t)(m0+mmv[p])*K + k0+kkv[p]];
                p2[p] = s_raw [(size_t)(m0+mmv[p])*K + k0+kkv[p]];
                p3[p] = ada_w_s [(size_t)(n0+mmv[p])*K + k0+kkv[p]];
                p4[p] = ada_w_nb[(size_t)(n0+mmv[p])*K + k0+kkv[p]];
                p5[p] = w_last  [(size_t)(n0+mmv[p])*K + k0+kkv[p]];
            }
        }
        #pragma unroll
        for(int kk=0;kk<16;kk++){
            float4 a1 = *(const float4*)&As1[buf][kk][ty*4];
            float4 a2 = *(const float4*)&As2[buf][kk][ty*4];
            ulonglong2 b1 = *(const ulonglong2*)&Bs1[buf][kk][tx*4];
            ulonglong2 b2 = *(const ulonglong2*)&Bs2[buf][kk][tx*4];
            ulonglong2 b3 = *(const ulonglong2*)&Bs3[buf][kk][tx*4];
            U64 a1d[4], a2d[4];
            a1d[0]=pk2(a1.x,a1.x); a1d[1]=pk2(a1.y,a1.y); a1d[2]=pk2(a1.z,a1.z); a1d[3]=pk2(a1.w,a1.w);
            a2d[0]=pk2(a2.x,a2.x); a2d[1]=pk2(a2.y,a2.y); a2d[2]=pk2(a2.z,a2.z); a2d[3]=pk2(a2.w,a2.w);
            #pragma unroll
            for(int i=0;i<4;i++){
                fma2(c1[i][0],a1d[i],b1.x); fma2(c1[i][1],a1d[i],b1.y);
                fma2(c2[i][0],a1d[i],b2.x); fma2(c2[i][1],a1d[i],b2.y);
                fma2(c3[i][0],a2d[i],b3.x); fma2(c3[i][1],a2d[i],b3.y);
            }
        }
        if(t < K/16-1){
            #pragma unroll
            for(int p=0;p<4;p++){
                As1[buf^1][kkv[p]][mmv[p]]=p1[p]; As2[buf^1][kkv[p]][mmv[p]]=p2[p];
                Bs1[buf^1][kkv[p]][mmv[p]]=p3[p]; Bs2[buf^1][kkv[p]][mmv[p]]=p4[p]; Bs3[buf^1][kkv[p]][mmv[p]]=p5[p];
            }
            __syncthreads();
            buf ^= 1;
        }
    }
    #pragma unroll
    for(int i=0;i<4;i++){
        int m = m0 + ty*4 + i;
        #pragma unroll
        for(int jp=0;jp<2;jp++){
            float2 v1 = up2(c1[i][jp]), v2 = up2(c2[i][jp]), v3 = up2(c3[i][jp]);
            int n = n0 + tx*4 + jp*2;
            float sgA = sigm(v1.x + ada_b_s[n]);
            float sgB = sigm(v1.y + ada_b_s[n+1]);
            g_anorm[(size_t)m*CA + n]   = sgA * g_a_ln[(size_t)m*CA + n]   + v2.x;
            g_anorm[(size_t)m*CA + n+1] = sgB * g_a_ln[(size_t)m*CA + n+1] + v2.y;
            g_glast[(size_t)m*CA + n]   = sigm(v3.x + b_last[n]);
            g_glast[(size_t)m*CA + n+1] = sigm(v3.y + b_last[n+1]);
        }
    }
}

// -------------------- kernel 3: QKVG projections (f32x2, double-buffered, n-offset) ----
__global__ __launch_bounds__(256) void qkvg_kernel(
    const float* __restrict__ wq, const float* __restrict__ bq,
    const float* __restrict__ wk, const float* __restrict__ bk,
    const float* __restrict__ wv, const float* __restrict__ bv,
    const float* __restrict__ wg, const float* __restrict__ bg,
    int nbase)
{
    const int K = CA;
    __shared__ __align__(16) float As[2][16][136];
    __shared__ __align__(16) float Bs[2][16][136];
    int tid = threadIdx.x;
    int tx = tid & 15, ty = tid >> 4;
    int m0 = blockIdx.y*128;
    int n0 = nbase + blockIdx.x*128;
    int which = n0 >> 9;
    int nn0 = n0 & 511;
    const float* W  = (which==0)?wq : (which==1)?wk : (which==2)?wv : wg;
    const float* Bv = (which==0)?bq : (which==1)?bk : (which==2)?bv : bg;
    U64 c[8][4]={};

    float pa[8], pb[8];
    int mmv[8], kkv[8];
    #pragma unroll
    for(int p=0;p<8;p++){ int e = p*256 + tid; mmv[p]=e>>4; kkv[p]=e&15; }

    #pragma unroll
    for(int p=0;p<8;p++){
        pa[p] = g_anorm[(size_t)(m0+mmv[p])*K + kkv[p]];
        pb[p] = W[(size_t)(nn0+mmv[p])*K + kkv[p]];
    }
    #pragma unroll
    for(int p=0;p<8;p++){ As[0][kkv[p]][mmv[p]]=pa[p]; Bs[0][kkv[p]][mmv[p]]=pb[p]; }
    __syncthreads();

    int buf = 0;
    for(int t=0;t<K/16;t++){
        if(t < K/16-1){
            int k0 = (t+1)*16;
            #pragma unroll
            for(int p=0;p<8;p++){
                pa[p] = g_anorm[(size_t)(m0+mmv[p])*K + k0+kkv[p]];
                pb[p] = W[(size_t)(nn0+mmv[p])*K + k0+kkv[p]];
            }
        }
        #pragma unroll
        for(int kk=0;kk<16;kk++){
            float4 t0 = *(const float4*)&As[buf][kk][ty*8];
            float4 t1 = *(const float4*)&As[buf][kk][ty*8+4];
            ulonglong2 b0 = *(const ulonglong2*)&Bs[buf][kk][tx*8];
            ulonglong2 b1 = *(const ulonglong2*)&Bs[buf][kk][tx*8+4];
            U64 ad[8];
            ad[0]=pk2(t0.x,t0.x); ad[1]=pk2(t0.y,t0.y); ad[2]=pk2(t0.z,t0.z); ad[3]=pk2(t0.w,t0.w);
            ad[4]=pk2(t1.x,t1.x); ad[5]=pk2(t1.y,t1.y); ad[6]=pk2(t1.z,t1.z); ad[7]=pk2(t1.w,t1.w);
            #pragma unroll
            for(int i=0;i<8;i++){
                fma2(c[i][0],ad[i],b0.x); fma2(c[i][1],ad[i],b0.y);
                fma2(c[i][2],ad[i],b1.x); fma2(c[i][3],ad[i],b1.y);
            }
        }
        if(t < K/16-1){
            #pragma unroll
            for(int p=0;p<8;p++){ As[buf^1][kkv[p]][mmv[p]]=pa[p]; Bs[buf^1][kkv[p]][mmv[p]]=pb[p]; }
            __syncthreads();
            buf ^= 1;
        }
    }

    float* dst = (which==0)?g_q : (which==1)?g_k : g_v;
    #pragma unroll
    for(int i=0;i<8;i++){
        int m = m0 + ty*8 + i;
        #pragma unroll
        for(int jp=0;jp<4;jp++){
            float2 v = up2(c[i][jp]);
            #pragma unroll
            for(int l=0;l<2;l++){
                int nn = nn0 + tx*8 + jp*2 + l;
                float val = (l?v.y:v.x) + Bv[nn];
                if(which < 3){
                    int hh = nn>>5, dd2 = nn&31;
                    int bb = m>>10, ll = m&1023;
                    dst[(((size_t)(bb*HH+hh))*LL + ll)*DD + dd2] = val;
                } else {
                    g_g[(size_t)m*CA + nn] = val;
                }
            }
        }
    }
}

// -------------------- kernel 4: pair bias (mask-skip, no dead stores) ----------
__global__ __launch_bounds__(256) void bias_kernel(
    const float* __restrict__ z, const float* __restrict__ z_scale,
    const float* __restrict__ wz, const int* __restrict__ mask)
{
    __shared__ __align__(16) U64 wzs2[HH][CZ/2];
    __shared__ float wsum[HH];
    int tid = threadIdx.x;
    for(int e=tid;e<HH*(CZ/2);e+=256){
        int h = e>>5, c2 = e&31;
        float w0 = wz[h*CZ + 2*c2    ]*z_scale[2*c2    ];
        float w1 = wz[h*CZ + 2*c2 + 1]*z_scale[2*c2 + 1];
        wzs2[h][c2] = pk2(w0,w1);
    }
    __syncthreads();
    if(tid < HH){
        float S=0.f;
        for(int c2=0;c2<CZ/2;c2++){ float2 t=up2(wzs2[tid][c2]); S += t.x + t.y; }
        wsum[tid]=S;
    }
    __syncthreads();

    size_t t0 = (size_t)blockIdx.x*256 + tid;
    int b_ = (int)(t0>>20), q_ = (int)((t0>>10)&1023), k_ = (int)(t0&1023);

    bool active = (mask[b_*LL + q_] != 0) && (mask[b_*LL + k_] != 0);
    if(!active) return;

    size_t ob = (((size_t)(b_*HH))*LL + q_)*LL + k_;
    const float4* zp = (const float4*)(z + t0*CZ);
    U64 acc[HH];
    #pragma unroll
    for(int h=0;h<HH;h++) acc[h]=0ull;
    U64 sum=0ull, ssq=0ull;
    const U64 one2 = pk2(1.f,1.f);

    #pragma unroll
    for(int cs=0;cs<16;cs++){
        float4 a = zp[cs];
        U64 p01 = pk2(a.x,a.y);
        U64 p23 = pk2(a.z,a.w);
        fma2(sum,p01,one2); fma2(sum,p23,one2);
        fma2(ssq,p01,p01);  fma2(ssq,p23,p23);
        #pragma unroll
        for(int h=0;h<HH;h++){
            ulonglong2 w = *(const ulonglong2*)&wzs2[h][cs*2];
            fma2(acc[h],p01,w.x);
            fma2(acc[h],p23,w.y);
        }
    }
    float2 s2=up2(sum), q2=up2(ssq);
    float mean = (s2.x+s2.y)*(1.f/CZ);
    float var  = (q2.x+q2.y)*(1.f/CZ) - mean*mean;
    float rstd = rsqrtf(var + 1e-5f);

    #pragma unroll
    for(int h=0;h<HH;h++){
        float2 d = up2(acc[h]);
        float v = rstd*((d.x+d.y) - mean*wsum[h]);
        g_biash[ob + (size_t)h*LL*LL] = __float2half(v);
    }
}

// -------------------- kernel 5: attention (round-8/11 version: key-skip only) ------
__global__ __launch_bounds__(128) void attn_kernel(const int* __restrict__ mask)
{
    __shared__ __align__(16) float Ks[64*32];
    __shared__ __align__(16) float Vs[64*32];
    __shared__ __align__(16) __half bsh[64][80];
    __shared__ float mk[64];

    int tid = threadIdx.x;          // 128
    int b = blockIdx.z, h = blockIdx.y;
    int q0 = blockIdx.x*64;
    int row = tid >> 1;             // 0..63
    int half = tid & 1;             // which 16-d half

    const float* qp = g_q + (((size_t)(b*HH+h))*LL + q0+row)*DD + half*16;
    U64 qr2[8];
    #pragma unroll
    for(int i=0;i<4;i++){
        float4 t4 = ((const float4*)qp)[i];
        qr2[i*2]   = pk2(t4.x*SCALE, t4.y*SCALE);
        qr2[i*2+1] = pk2(t4.z*SCALE, t4.w*SCALE);
    }
    U64 O2[8];
    #pragma unroll
    for(int i=0;i<8;i++) O2[i]=0ull;
    float lrun = 0.f;

    const float* Kbase = g_k + ((size_t)(b*HH+h))*LL*DD;
    const float* Vbase = g_v + ((size_t)(b*HH+h))*LL*DD;
    const __half* bbase = g_biash + (((size_t)(b*HH+h))*LL + q0)*LL;

    for(int kt=0; kt<LL; kt+=64){
        __syncthreads();
        #pragma unroll
        for(int p=0;p<4;p++){
            int f = p*128 + tid;  // 512 float4s
            ((float4*)Ks)[f] = ((const float4*)(Kbase + (size_t)kt*DD))[f];
            ((float4*)Vs)[f] = ((const float4*)(Vbase + (size_t)kt*DD))[f];
        }
        #pragma unroll
        for(int p=0;p<4;p++){
            int c = p*128 + tid;   // 512 chunks of 8 halves
            int r = c>>3, part = c&7;
            *(float4*)&bsh[r][part*8] = ((const float4*)(bbase + (size_t)r*LL + kt))[part];
        }
        if(tid < 64) mk[tid] = mask[b*LL + kt + tid] ? 0.f : -10000.f;
        __syncthreads();

        for(int j0=0;j0<64;j0+=4){
            const __half2* bp = (const __half2*)&bsh[row][j0];
            float2 b01 = __half22float2(bp[0]);
            float2 b23 = __half22float2(bp[1]);
            float bb4[4] = {b01.x, b01.y, b23.x, b23.y};
            #pragma unroll
            for(int jj=0;jj<4;jj++){
                int j = j0 + jj;
                if(mk[j] == 0.f){   // uniform across block: skip masked keys (exp==0)
                    const ulonglong2* kp = (const ulonglong2*)&Ks[j*32 + half*16];
                    U64 sacc = 0ull;
                    #pragma unroll
                    for(int i=0;i<4;i++){
                        ulonglong2 kv = kp[i];
                        fma2(sacc, qr2[i*2],   kv.x);
                        fma2(sacc, qr2[i*2+1], kv.y);
                    }
                    float2 sp = up2(sacc);
                    float part = sp.x + sp.y;
                    float tot = part + __shfl_xor_sync(0xffffffffu, part, 1);
                    float s_ = tot + bb4[jj];
                    float p_ = __expf(s_);
                    lrun += p_;
                    U64 pp = pk2(p_, p_);
                    const ulonglong2* vp = (const ulonglong2*)&Vs[j*32 + half*16];
                    #pragma unroll
                    for(int i=0;i<4;i++){
                        ulonglong2 vv = vp[i];
                        fma2(O2[i*2],   pp, vv.x);
                        fma2(O2[i*2+1], pp, vv.y);
                    }
                }
            }
        }
    }
    float inv = 1.f/fmaxf(lrun, 1e-20f);
    float* dst = g_ao + ((size_t)(b*LL + q0+row))*CA + h*DD + half*16;
    #pragma unroll
    for(int i=0;i<4;i++){
        float2 v0 = up2(O2[i*2]), v1 = up2(O2[i*2+1]);
        ((float4*)dst)[i] = make_float4(v0.x*inv, v0.y*inv, v1.x*inv, v1.y*inv);
    }
}

// -------------------- kernel 6: output GEMM (f32x2) --------------------
__global__ __launch_bounds__(256) void out_kernel(
    const float* __restrict__ wo, const float* __restrict__ bo,
    const int* __restrict__ mask, float* __restrict__ out)
{
    const int K = CA;
    __shared__ __align__(16) float As[16][72];
    __shared__ __align__(16) float Bs[16][72];
    int tid = threadIdx.x;
    int tx = tid & 15, ty = tid >> 4;
    int m0 = blockIdx.y*64, n0 = blockIdx.x*64;
    U64 c[4][2]={};
    for(int k0=0;k0<K;k0+=16){
        #pragma unroll
        for(int p=0;p<4;p++){
            int e = p*256 + tid;
            int mm = e>>4, kk = e&15;
            size_t ai = (size_t)(m0+mm)*K + k0+kk;
            As[kk][mm] = sigm(g_g[ai]) * g_ao[ai];
            Bs[kk][mm] = wo[(size_t)(n0+mm)*K + k0+kk];
        }
        __syncthreads();
        #pragma unroll
        for(int kk=0;kk<16;kk++){
            float4 a4 = *(const float4*)&As[kk][ty*4];
            ulonglong2 bu = *(const ulonglong2*)&Bs[kk][tx*4];
            U64 ad[4];
            ad[0]=pk2(a4.x,a4.x); ad[1]=pk2(a4.y,a4.y); ad[2]=pk2(a4.z,a4.z); ad[3]=pk2(a4.w,a4.w);
            #pragma unroll
            for(int i=0;i<4;i++){
                fma2(c[i][0],ad[i],bu.x);
                fma2(c[i][1],ad[i],bu.y);
            }
        }
        __syncthreads();
    }
    #pragma unroll
    for(int i=0;i<4;i++){
        int m = m0 + ty*4 + i;
        float mq = mask[m] ? 1.f : 0.f;
        #pragma unroll
        for(int jp=0;jp<2;jp++){
            float2 v = up2(c[i][jp]);
            int n = n0 + tx*4 + jp*2;
            out[(size_t)m*CA + n]   = (v.x + bo[n])   * g_glast[(size_t)m*CA + n]   * mq;
            out[(size_t)m*CA + n+1] = (v.y + bo[n+1]) * g_glast[(size_t)m*CA + n+1] * mq;
        }
    }
}

// -------------------- launch (two-branch overlap) ----------
extern "C" void kernel_launch(void* const* d_in, const int* in_sizes, int n_in,
                              void* d_out, int out_size)
{
    const float* a          = (const float*)d_in[0];
    const float* s          = (const float*)d_in[1];
    const float* z          = (const float*)d_in[2];
    const float* ln_s_scale = (const float*)d_in[3];
    const float* ada_w_s    = (const float*)d_in[4];
    const float* ada_b_s    = (const float*)d_in[5];
    const float* ada_w_nb   = (const float*)d_in[6];
    const float* wq = (const float*)d_in[7];  const float* bq = (const float*)d_in[8];
    const float* wk = (const float*)d_in[9];  const float* bk = (const float*)d_in[10];
    const float* wv = (const float*)d_in[11]; const float* bv = (const float*)d_in[12];
    const float* wg = (const float*)d_in[13]; const float* bg = (const float*)d_in[14];
    const float* wo = (const float*)d_in[15]; const float* bo = (const float*)d_in[16];
    const float* ln_z_scale = (const float*)d_in[17];
    const float* wz         = (const float*)d_in[18];
    const float* w_last     = (const float*)d_in[19];
    const float* b_last     = (const float*)d_in[20];
    const int*   mask       = (const int*)d_in[21];
    float* out = (float*)d_out;

    static cudaStream_t s_side = 0;
    static cudaEvent_t ev_fork = 0, ev_bias = 0, ev_anorm = 0, ev_g = 0;
    if(!s_side){
        cudaStreamCreateWithFlags(&s_side, cudaStreamNonBlocking);
        cudaEventCreateWithFlags(&ev_fork,  cudaEventDisableTiming);
        cudaEventCreateWithFlags(&ev_bias,  cudaEventDisableTiming);
        cudaEventCreateWithFlags(&ev_anorm, cudaEventDisableTiming);
        cudaEventCreateWithFlags(&ev_g,     cudaEventDisableTiming);
    }

    // fork: bias branch (depends only on z, ln_z_scale, wz, mask)
    cudaEventRecord(ev_fork, 0);
    cudaStreamWaitEvent(s_side, ev_fork, 0);
    bias_kernel<<<(BB*LL*LL)/256, 256, 0, s_side>>>(z, ln_z_scale, wz, mask);
    cudaEventRecord(ev_bias, s_side);

    // main branch: ln -> anorm -> qkv
    ln_kernel<<<MM, 256>>>(a, s, ln_s_scale);
    anorm_kernel<<<dim3(CA/64, MM/64), 256>>>(s, ada_w_s, ada_b_s, ada_w_nb, w_last, b_last);
    cudaEventRecord(ev_anorm, 0);
    qkvg_kernel<<<dim3(1536/128, MM/128), 256>>>(wq,bq, wk,bk, wv,bv, wg,bg, 0);      // Q,K,V

    // side: G projection after anorm & bias, overlaps with attention
    cudaStreamWaitEvent(s_side, ev_anorm, 0);
    qkvg_kernel<<<dim3(512/128, MM/128), 256, 0, s_side>>>(wq,bq, wk,bk, wv,bv, wg,bg, 1536); // G
    cudaEventRecord(ev_g, s_side);

    // join: attention needs bias + q/k/v
    cudaStreamWaitEvent(0, ev_bias, 0);
    attn_kernel<<<dim3(LL/64, HH, BB), 128>>>(mask);

    // out needs g too
    cudaStreamWaitEvent(0, ev_g, 0);
    out_kernel<<<dim3(CA/64, MM/64), 256>>>(wo, bo, mask, out);
}

// round 15
// speedup vs baseline: 1.0445x; 1.0139x over previous
#include <cuda_runtime.h>
#include <cuda_bf16.h>
#include <cuda_fp16.h>

// Problem constants
#define BB 2
#define LL 1024
#define CA 512
#define CS 384
#define CZ 64
#define HH 16
#define DD 32
#define MM (BB*LL)          // 2048 rows
#define SCALE 0.17677669529663687f  // 1/sqrt(32)

typedef unsigned long long U64;
__device__ __forceinline__ U64 pk2(float lo, float hi){ U64 r; asm("mov.b64 %0, {%1,%2};":"=l"(r):"f"(lo),"f"(hi)); return r; }
__device__ __forceinline__ void fma2(U64 &d, U64 a, U64 b){ asm("fma.rn.f32x2 %0, %1, %2, %3;":"=l"(d):"l"(a),"l"(b),"l"(d)); }
__device__ __forceinline__ float2 up2(U64 v){ float2 r; asm("mov.b64 {%0,%1}, %2;":"=f"(r.x),"=f"(r.y):"l"(v)); return r; }

// -------------------- device scratch --------------------
__device__ __align__(16) float g_s_ln[MM*CS];
__device__ __align__(16) float g_a_ln[MM*CA];
__device__ __align__(16) float g_anorm[MM*CA];
__device__ __align__(16) float g_glast[MM*CA];
__device__ __align__(16) float g_q[MM*CA];   // [b][h][l][d]
__device__ __align__(16) float g_k[MM*CA];
__device__ __align__(16) float g_v[MM*CA];
__device__ __align__(16) float g_g[MM*CA];   // pre-sigmoid gate
__device__ __align__(16) float g_ao[MM*CA];  // attention out [b][l][h*32+d]
__device__ __align__(16) __half g_biash[(size_t)BB*HH*LL*LL]; // 67MB fp16 bias

__device__ __forceinline__ float sigm(float x){ return 1.f/(1.f+__expf(-x)); }

// -------------------- kernel 1: row layernorms --------------------
__global__ __launch_bounds__(256) void ln_kernel(
    const float* __restrict__ a, const float* __restrict__ s,
    const float* __restrict__ s_scale)
{
    int row = blockIdx.x;
    int tid = threadIdx.x;
    __shared__ float rs[16];
    const float* ar = a + (size_t)row*CA;
    float x0 = ar[tid], x1 = ar[tid+256];
    float sum = x0+x1, ss = x0*x0 + x1*x1;
    #pragma unroll
    for(int o=16;o;o>>=1){ sum += __shfl_xor_sync(0xffffffffu,sum,o); ss += __shfl_xor_sync(0xffffffffu,ss,o); }
    if((tid&31)==0){ rs[tid>>5]=sum; rs[8+(tid>>5)]=ss; }
    __syncthreads();
    if(tid==0){ float S=0,Q=0; for(int i=0;i<8;i++){S+=rs[i];Q+=rs[8+i];} rs[0]=S; rs[8]=Q; }
    __syncthreads();
    float mean = rs[0]*(1.f/CA);
    float var  = rs[8]*(1.f/CA) - mean*mean;
    float rstd = rsqrtf(var + 1e-5f);
    g_a_ln[(size_t)row*CA + tid]      = (x0-mean)*rstd;
    g_a_ln[(size_t)row*CA + tid+256]  = (x1-mean)*rstd;
    __syncthreads();
    const float* sr = s + (size_t)row*CS;
    float y0 = sr[tid];
    float y1 = (tid < CS-256) ? sr[tid+256] : 0.f;
    sum = y0+y1; ss = y0*y0 + y1*y1;
    #pragma unroll
    for(int o=16;o;o>>=1){ sum += __shfl_xor_sync(0xffffffffu,sum,o); ss += __shfl_xor_sync(0xffffffffu,ss,o); }
    if((tid&31)==0){ rs[tid>>5]=sum; rs[8+(tid>>5)]=ss; }
    __syncthreads();
    if(tid==0){ float S=0,Q=0; for(int i=0;i<8;i++){S+=rs[i];Q+=rs[8+i];} rs[0]=S; rs[8]=Q; }
    __syncthreads();
    mean = rs[0]*(1.f/CS);
    var  = rs[8]*(1.f/CS) - mean*mean;
    rstd = rsqrtf(var + 1e-5f);
    g_s_ln[(size_t)row*CS + tid] = (y0-mean)*rstd*s_scale[tid];
    if(tid < CS-256)
        g_s_ln[(size_t)row*CS + tid+256] = (y1-mean)*rstd*s_scale[tid+256];
}

// -------------------- kernel 2: a_norm + glast (triple GEMM, f32x2) --------------------
__global__ __launch_bounds__(256) void anorm_kernel(
    const float* __restrict__ s_raw,
    const float* __restrict__ ada_w_s, const float* __restrict__ ada_b_s,
    const float* __restrict__ ada_w_nb,
    const float* __restrict__ w_last, const float* __restrict__ b_last)
{
    const int K = CS;
    __shared__ __align__(16) float As1[16][72];
    __shared__ __align__(16) float As2[16][72];
    __shared__ __align__(16) float Bs1[16][72];
    __shared__ __align__(16) float Bs2[16][72];
    __shared__ __align__(16) float Bs3[16][72];
    int tid = threadIdx.x;
    int tx = tid & 15, ty = tid >> 4;
    int m0 = blockIdx.y*64, n0 = blockIdx.x*64;
    U64 c1[4][2]={}, c2[4][2]={}, c3[4][2]={};
    for(int k0=0;k0<K;k0+=16){
        #pragma unroll
        for(int p=0;p<4;p++){
            int e = p*256 + tid;
            int mm = e>>4, kk = e&15;
            As1[kk][mm] = g_s_ln[(size_t)(m0+mm)*K + k0+kk];
            As2[kk][mm] = s_raw[(size_t)(m0+mm)*K + k0+kk];
            Bs1[kk][mm] = ada_w_s [(size_t)(n0+mm)*K + k0+kk];
            Bs2[kk][mm] = ada_w_nb[(size_t)(n0+mm)*K + k0+kk];
            Bs3[kk][mm] = w_last  [(size_t)(n0+mm)*K + k0+kk];
        }
        __syncthreads();
        #pragma unroll
        for(int kk=0;kk<16;kk++){
            float4 a1 = *(const float4*)&As1[kk][ty*4];
            float4 a2 = *(const float4*)&As2[kk][ty*4];
            ulonglong2 b1 = *(const ulonglong2*)&Bs1[kk][tx*4];
            ulonglong2 b2 = *(const ulonglong2*)&Bs2[kk][tx*4];
            ulonglong2 b3 = *(const ulonglong2*)&Bs3[kk][tx*4];
            U64 a1d[4], a2d[4];
            a1d[0]=pk2(a1.x,a1.x); a1d[1]=pk2(a1.y,a1.y); a1d[2]=pk2(a1.z,a1.z); a1d[3]=pk2(a1.w,a1.w);
            a2d[0]=pk2(a2.x,a2.x); a2d[1]=pk2(a2.y,a2.y); a2d[2]=pk2(a2.z,a2.z); a2d[3]=pk2(a2.w,a2.w);
            #pragma unroll
            for(int i=0;i<4;i++){
                fma2(c1[i][0],a1d[i],b1.x); fma2(c1[i][1],a1d[i],b1.y);
                fma2(c2[i][0],a1d[i],b2.x); fma2(c2[i][1],a1d[i],b2.y);
                fma2(c3[i][0],a2d[i],b3.x); fma2(c3[i][1],a2d[i],b3.y);
            }
        }
        __syncthreads();
    }
    #pragma unroll
    for(int i=0;i<4;i++){
        int m = m0 + ty*4 + i;
        #pragma unroll
        for(int jp=0;jp<2;jp++){
            float2 v1 = up2(c1[i][jp]), v2 = up2(c2[i][jp]), v3 = up2(c3[i][jp]);
            int n = n0 + tx*4 + jp*2;
            float sgA = sigm(v1.x + ada_b_s[n]);
            float sgB = sigm(v1.y + ada_b_s[n+1]);
            g_anorm[(size_t)m*CA + n]   = sgA * g_a_ln[(size_t)m*CA + n]   + v2.x;
            g_anorm[(size_t)m*CA + n+1] = sgB * g_a_ln[(size_t)m*CA + n+1] + v2.y;
            g_glast[(size_t)m*CA + n]   = sigm(v3.x + b_last[n]);
            g_glast[(size_t)m*CA + n+1] = sigm(v3.y + b_last[n+1]);
        }
    }
}

// -------------------- kernel 3: QKVG projections (f32x2, double-buffered) ----------
__global__ __launch_bounds__(256) void qkvg_kernel(
    const float* __restrict__ wq, const float* __restrict__ bq,
    const float* __restrict__ wk, const float* __restrict__ bk,
    const float* __restrict__ wv, const float* __restrict__ bv,
    const float* __restrict__ wg, const float* __restrict__ bg)
{
    const int K = CA;
    __shared__ __align__(16) float As[2][16][136];
    __shared__ __align__(16) float Bs[2][16][136];
    int tid = threadIdx.x;
    int tx = tid & 15, ty = tid >> 4;
    int m0 = blockIdx.y*128;
    int n0 = blockIdx.x*128;
    int which = n0 >> 9;
    int nn0 = n0 & 511;
    const float* W  = (which==0)?wq : (which==1)?wk : (which==2)?wv : wg;
    const float* Bv = (which==0)?bq : (which==1)?bk : (which==2)?bv : bg;
    U64 c[8][4]={};

    float pa[8], pb[8];
    int mmv[8], kkv[8];
    #pragma unroll
    for(int p=0;p<8;p++){ int e = p*256 + tid; mmv[p]=e>>4; kkv[p]=e&15; }

    #pragma unroll
    for(int p=0;p<8;p++){
        pa[p] = g_anorm[(size_t)(m0+mmv[p])*K + kkv[p]];
        pb[p] = W[(size_t)(nn0+mmv[p])*K + kkv[p]];
    }
    #pragma unroll
    for(int p=0;p<8;p++){ As[0][kkv[p]][mmv[p]]=pa[p]; Bs[0][kkv[p]][mmv[p]]=pb[p]; }
    __syncthreads();

    int buf = 0;
    for(int t=0;t<K/16;t++){
        if(t < K/16-1){
            int k0 = (t+1)*16;
            #pragma unroll
            for(int p=0;p<8;p++){
                pa[p] = g_anorm[(size_t)(m0+mmv[p])*K + k0+kkv[p]];
                pb[p] = W[(size_t)(nn0+mmv[p])*K + k0+kkv[p]];
            }
        }
        #pragma unroll
        for(int kk=0;kk<16;kk++){
            float4 t0 = *(const float4*)&As[buf][kk][ty*8];
            float4 t1 = *(const float4*)&As[buf][kk][ty*8+4];
            ulonglong2 b0 = *(const ulonglong2*)&Bs[buf][kk][tx*8];
            ulonglong2 b1 = *(const ulonglong2*)&Bs[buf][kk][tx*8+4];
            U64 ad[8];
            ad[0]=pk2(t0.x,t0.x); ad[1]=pk2(t0.y,t0.y); ad[2]=pk2(t0.z,t0.z); ad[3]=pk2(t0.w,t0.w);
            ad[4]=pk2(t1.x,t1.x); ad[5]=pk2(t1.y,t1.y); ad[6]=pk2(t1.z,t1.z); ad[7]=pk2(t1.w,t1.w);
            #pragma unroll
            for(int i=0;i<8;i++){
                fma2(c[i][0],ad[i],b0.x); fma2(c[i][1],ad[i],b0.y);
                fma2(c[i][2],ad[i],b1.x); fma2(c[i][3],ad[i],b1.y);
            }
        }
        if(t < K/16-1){
            #pragma unroll
            for(int p=0;p<8;p++){ As[buf^1][kkv[p]][mmv[p]]=pa[p]; Bs[buf^1][kkv[p]][mmv[p]]=pb[p]; }
            __syncthreads();
            buf ^= 1;
        }
    }

    float* dst = (which==0)?g_q : (which==1)?g_k : g_v;
    #pragma unroll
    for(int i=0;i<8;i++){
        int m = m0 + ty*8 + i;
        #pragma unroll
        for(int jp=0;jp<4;jp++){
            float2 v = up2(c[i][jp]);
            #pragma unroll
            for(int l=0;l<2;l++){
                int nn = nn0 + tx*8 + jp*2 + l;
                float val = (l?v.y:v.x) + Bv[nn];
                if(which < 3){
                    int hh = nn>>5, dd2 = nn&31;
                    int bb = m>>10, ll = m&1023;
                    dst[(((size_t)(bb*HH+hh))*LL + ll)*DD + dd2] = val;
                } else {
                    g_g[(size_t)m*CA + nn] = val;
                }
            }
        }
    }
}

// -------------------- kernel 4: pair bias (mask-skip, no dead stores) ----------
__global__ __launch_bounds__(256) void bias_kernel(
    const float* __restrict__ z, const float* __restrict__ z_scale,
    const float* __restrict__ wz, const int* __restrict__ mask)
{
    __shared__ __align__(16) U64 wzs2[HH][CZ/2];
    __shared__ float wsum[HH];
    int tid = threadIdx.x;
    for(int e=tid;e<HH*(CZ/2);e+=256){
        int h = e>>5, c2 = e&31;
        float w0 = wz[h*CZ + 2*c2    ]*z_scale[2*c2    ];
        float w1 = wz[h*CZ + 2*c2 + 1]*z_scale[2*c2 + 1];
        wzs2[h][c2] = pk2(w0,w1);
    }
    __syncthreads();
    if(tid < HH){
        float S=0.f;
        for(int c2=0;c2<CZ/2;c2++){ float2 t=up2(wzs2[tid][c2]); S += t.x + t.y; }
        wsum[tid]=S;
    }
    __syncthreads();

    size_t t0 = (size_t)blockIdx.x*256 + tid;
    int b_ = (int)(t0>>20), q_ = (int)((t0>>10)&1023), k_ = (int)(t0&1023);

    bool active = (mask[b_*LL + q_] != 0) && (mask[b_*LL + k_] != 0);
    if(!active) return;

    size_t ob = (((size_t)(b_*HH))*LL + q_)*LL + k_;
    const float4* zp = (const float4*)(z + t0*CZ);
    U64 acc[HH];
    #pragma unroll
    for(int h=0;h<HH;h++) acc[h]=0ull;
    U64 sum=0ull, ssq=0ull;
    const U64 one2 = pk2(1.f,1.f);

    #pragma unroll
    for(int cs=0;cs<16;cs++){
        float4 a = zp[cs];
        U64 p01 = pk2(a.x,a.y);
        U64 p23 = pk2(a.z,a.w);
        fma2(sum,p01,one2); fma2(sum,p23,one2);
        fma2(ssq,p01,p01);  fma2(ssq,p23,p23);
        #pragma unroll
        for(int h=0;h<HH;h++){
            ulonglong2 w = *(const ulonglong2*)&wzs2[h][cs*2];
            fma2(acc[h],p01,w.x);
            fma2(acc[h],p23,w.y);
        }
    }
    float2 s2=up2(sum), q2=up2(ssq);
    float mean = (s2.x+s2.y)*(1.f/CZ);
    float var  = (q2.x+q2.y)*(1.f/CZ) - mean*mean;
    float rstd = rsqrtf(var + 1e-5f);

    #pragma unroll
    for(int h=0;h<HH;h++){
        float2 d = up2(acc[h]);
        float v = rstd*((d.x+d.y) - mean*wsum[h]);
        g_biash[ob + (size_t)h*LL*LL] = __float2half(v);
    }
}

// -------------------- kernel 5: attention (key-skip, direct gmem bias read) ------
__global__ __launch_bounds__(128) void attn_kernel(const int* __restrict__ mask)
{
    __shared__ __align__(16) float Ks[64*32];
    __shared__ __align__(16) float Vs[64*32];
    __shared__ float mk[64];

    int tid = threadIdx.x;          // 128
    int b = blockIdx.z, h = blockIdx.y;
    int q0 = blockIdx.x*64;
    int row = tid >> 1;             // 0..63
    int half = tid & 1;             // which 16-d half

    const float* qp = g_q + (((size_t)(b*HH+h))*LL + q0+row)*DD + half*16;
    U64 qr2[8];
    #pragma unroll
    for(int i=0;i<4;i++){
        float4 t4 = ((const float4*)qp)[i];
        qr2[i*2]   = pk2(t4.x*SCALE, t4.y*SCALE);
        qr2[i*2+1] = pk2(t4.z*SCALE, t4.w*SCALE);
    }
    U64 O2[8];
    #pragma unroll
    for(int i=0;i<8;i++) O2[i]=0ull;
    float lrun = 0.f;

    const float* Kbase = g_k + ((size_t)(b*HH+h))*LL*DD;
    const float* Vbase = g_v + ((size_t)(b*HH+h))*LL*DD;
    const __half* brow = g_biash + (((size_t)(b*HH+h))*LL + q0+row)*LL;

    for(int kt=0; kt<LL; kt+=64){
        __syncthreads();
        #pragma unroll
        for(int p=0;p<4;p++){
            int f = p*128 + tid;  // 512 float4s
            ((float4*)Ks)[f] = ((const float4*)(Kbase + (size_t)kt*DD))[f];
            ((float4*)Vs)[f] = ((const float4*)(Vbase + (size_t)kt*DD))[f];
        }
        if(tid < 64) mk[tid] = mask[b*LL + kt + tid] ? 0.f : -10000.f;
        __syncthreads();

        for(int j0=0;j0<64;j0+=8){
            uint4 braw = *(const uint4*)(brow + kt + j0);   // 8 halves, broadcast in pair
            const __half2* hb = (const __half2*)&braw;
            #pragma unroll
            for(int g2=0;g2<4;g2++){
                float2 bf = __half22float2(hb[g2]);
                float bias2[2] = {bf.x, bf.y};
                #pragma unroll
                for(int l=0;l<2;l++){
                    int j = j0 + g2*2 + l;
                    if(mk[j] == 0.f){   // uniform across block: skip masked keys
                        const ulonglong2* kp = (const ulonglong2*)&Ks[j*32 + half*16];
                        U64 sacc = 0ull;
                        #pragma unroll
                        for(int i=0;i<4;i++){
                            ulonglong2 kv = kp[i];
                            fma2(sacc, qr2[i*2],   kv.x);
                            fma2(sacc, qr2[i*2+1], kv.y);
                        }
                        float2 sp = up2(sacc);
                        float part = sp.x + sp.y;
                        float tot = part + __shfl_xor_sync(0xffffffffu, part, 1);
                        float s_ = tot + bias2[l];
                        float p_ = __expf(s_);
                        lrun += p_;
                        U64 pp = pk2(p_, p_);
                        const ulonglong2* vp = (const ulonglong2*)&Vs[j*32 + half*16];
                        #pragma unroll
                        for(int i=0;i<4;i++){
                            ulonglong2 vv = vp[i];
                            fma2(O2[i*2],   pp, vv.x);
                            fma2(O2[i*2+1], pp, vv.y);
                        }
                    }
                }
            }
        }
    }
    float inv = 1.f/fmaxf(lrun, 1e-20f);
    float* dst = g_ao + ((size_t)(b*LL + q0+row))*CA + h*DD + half*16;
    #pragma unroll
    for(int i=0;i<4;i++){
        float2 v0 = up2(O2[i*2]), v1 = up2(O2[i*2+1]);
        ((float4*)dst)[i] = make_float4(v0.x*inv, v0.y*inv, v1.x*inv, v1.y*inv);
    }
}

// -------------------- kernel 6: output GEMM (f32x2) --------------------
__global__ __launch_bounds__(256) void out_kernel(
    const float* __restrict__ wo, const float* __restrict__ bo,
    const int* __restrict__ mask, float* __restrict__ out)
{
    const int K = CA;
    __shared__ __align__(16) float As[16][72];
    __shared__ __align__(16) float Bs[16][72];
    int tid = threadIdx.x;
    int tx = tid & 15, ty = tid >> 4;
    int m0 = blockIdx.y*64, n0 = blockIdx.x*64;
    U64 c[4][2]={};
    for(int k0=0;k0<K;k0+=16){
        #pragma unroll
        for(int p=0;p<4;p++){
            int e = p*256 + tid;
            int mm = e>>4, kk = e&15;
            size_t ai = (size_t)(m0+mm)*K + k0+kk;
            As[kk][mm] = sigm(g_g[ai]) * g_ao[ai];
            Bs[kk][mm] = wo[(size_t)(n0+mm)*K + k0+kk];
        }
        __syncthreads();
        #pragma unroll
        for(int kk=0;kk<16;kk++){
            float4 a4 = *(const float4*)&As[kk][ty*4];
            ulonglong2 bu = *(const ulonglong2*)&Bs[kk][tx*4];
            U64 ad[4];
            ad[0]=pk2(a4.x,a4.x); ad[1]=pk2(a4.y,a4.y); ad[2]=pk2(a4.z,a4.z); ad[3]=pk2(a4.w,a4.w);
            #pragma unroll
            for(int i=0;i<4;i++){
                fma2(c[i][0],ad[i],bu.x);
                fma2(c[i][1],ad[i],bu.y);
            }
        }
        __syncthreads();
    }
    #pragma unroll
    for(int i=0;i<4;i++){
        int m = m0 + ty*4 + i;
        float mq = mask[m] ? 1.f : 0.f;
        #pragma unroll
        for(int jp=0;jp<2;jp++){
            float2 v = up2(c[i][jp]);
            int n = n0 + tx*4 + jp*2;
            out[(size_t)m*CA + n]   = (v.x + bo[n])   * g_glast[(size_t)m*CA + n]   * mq;
            out[(size_t)m*CA + n+1] = (v.y + bo[n+1]) * g_glast[(size_t)m*CA + n+1] * mq;
        }
    }
}

// -------------------- launch (fork-join: bias overlaps ln/anorm/qkvg) ----------
extern "C" void kernel_launch(void* const* d_in, const int* in_sizes, int n_in,
                              void* d_out, int out_size)
{
    const float* a          = (const float*)d_in[0];
    const float* s          = (const float*)d_in[1];
    const float* z          = (const float*)d_in[2];
    const float* ln_s_scale = (const float*)d_in[3];
    const float* ada_w_s    = (const float*)d_in[4];
    const float* ada_b_s    = (const float*)d_in[5];
    const float* ada_w_nb   = (const float*)d_in[6];
    const float* wq = (const float*)d_in[7];  const float* bq = (const float*)d_in[8];
    const float* wk = (const float*)d_in[9];  const float* bk = (const float*)d_in[10];
    const float* wv = (const float*)d_in[11]; const float* bv = (const float*)d_in[12];
    const float* wg = (const float*)d_in[13]; const float* bg = (const float*)d_in[14];
    const float* wo = (const float*)d_in[15]; const float* bo = (const float*)d_in[16];
    const float* ln_z_scale = (const float*)d_in[17];
    const float* wz         = (const float*)d_in[18];
    const float* w_last     = (const float*)d_in[19];
    const float* b_last     = (const float*)d_in[20];
    const int*   mask       = (const int*)d_in[21];
    float* out = (float*)d_out;

    static cudaStream_t s_bias = 0;
    static cudaEvent_t ev_fork = 0, ev_join = 0;
    if(!s_bias){
        cudaStreamCreateWithFlags(&s_bias, cudaStreamNonBlocking);
        cudaEventCreateWithFlags(&ev_fork, cudaEventDisableTiming);
        cudaEventCreateWithFlags(&ev_join, cudaEventDisableTiming);
    }

    // fork: bias branch (depends only on z, ln_z_scale, wz, mask)
    cudaEventRecord(ev_fork, 0);
    cudaStreamWaitEvent(s_bias, ev_fork, 0);
    bias_kernel<<<(BB*LL*LL)/256, 256, 0, s_bias>>>(z, ln_z_scale, wz, mask);
    cudaEventRecord(ev_join, s_bias);

    // main branch
    ln_kernel<<<MM, 256>>>(a, s, ln_s_scale);
    anorm_kernel<<<dim3(CA/64, MM/64), 256>>>(s, ada_w_s, ada_b_s, ada_w_nb, w_last, b_last);
    qkvg_kernel<<<dim3(2048/128, MM/128), 256>>>(wq,bq, wk,bk, wv,bv, wg,bg);

    // join: attention needs both bias and q/k/v
    cudaStreamWaitEvent(0, ev_join, 0);
    attn_kernel<<<dim3(LL/64, HH, BB), 128>>>(mask);
    out_kernel<<<dim3(CA/64, MM/64), 256>>>(wo, bo, mask, out);
}

// round 16
// speedup vs baseline: 1.2647x; 1.2107x over previous
#include <cuda_runtime.h>
#include <cuda_bf16.h>
#include <cuda_fp16.h>

// Problem constants
#define BB 2
#define LL 1024
#define CA 512
#define CS 384
#define CZ 64
#define HH 16
#define DD 32
#define MM (BB*LL)          // 2048 rows
#define SCALE 0.17677669529663687f  // 1/sqrt(32)

typedef unsigned long long U64;
__device__ __forceinline__ U64 pk2(float lo, float hi){ U64 r; asm("mov.b64 %0, {%1,%2};":"=l"(r):"f"(lo),"f"(hi)); return r; }
__device__ __forceinline__ void fma2(U64 &d, U64 a, U64 b){ asm("fma.rn.f32x2 %0, %1, %2, %3;":"=l"(d):"l"(a),"l"(b),"l"(d)); }
__device__ __forceinline__ float2 up2(U64 v){ float2 r; asm("mov.b64 {%0,%1}, %2;":"=f"(r.x),"=f"(r.y):"l"(v)); return r; }
__device__ __forceinline__ unsigned f2tf(float f){ unsigned r; asm("cvt.rna.tf32.f32 %0, %1;":"=r"(r):"f"(f)); return r; }

// -------------------- device scratch --------------------
__device__ __align__(16) float g_s_ln[MM*CS];
__device__ __align__(16) float g_a_ln[MM*CA];
__device__ __align__(16) float g_anorm[MM*CA];
__device__ __align__(16) float g_glast[MM*CA];
__device__ __align__(16) float g_q[MM*CA];   // [b][h][l][d]
__device__ __align__(16) float g_k[MM*CA];
__device__ __align__(16) float g_v[MM*CA];
__device__ __align__(16) float g_g[MM*CA];   // pre-sigmoid gate
__device__ __align__(16) float g_ao[MM*CA];  // attention out [b][l][h*32+d]
__device__ __align__(16) __half g_biash[(size_t)BB*HH*LL*LL]; // 67MB fp16 bias

__device__ __forceinline__ float sigm(float x){ return 1.f/(1.f+__expf(-x)); }

// -------------------- kernel 1: row layernorms --------------------
__global__ __launch_bounds__(256) void ln_kernel(
    const float* __restrict__ a, const float* __restrict__ s,
    const float* __restrict__ s_scale)
{
    int row = blockIdx.x;
    int tid = threadIdx.x;
    __shared__ float rs[16];
    const float* ar = a + (size_t)row*CA;
    float x0 = ar[tid], x1 = ar[tid+256];
    float sum = x0+x1, ss = x0*x0 + x1*x1;
    #pragma unroll
    for(int o=16;o;o>>=1){ sum += __shfl_xor_sync(0xffffffffu,sum,o); ss += __shfl_xor_sync(0xffffffffu,ss,o); }
    if((tid&31)==0){ rs[tid>>5]=sum; rs[8+(tid>>5)]=ss; }
    __syncthreads();
    if(tid==0){ float S=0,Q=0; for(int i=0;i<8;i++){S+=rs[i];Q+=rs[8+i];} rs[0]=S; rs[8]=Q; }
    __syncthreads();
    float mean = rs[0]*(1.f/CA);
    float var  = rs[8]*(1.f/CA) - mean*mean;
    float rstd = rsqrtf(var + 1e-5f);
    g_a_ln[(size_t)row*CA + tid]      = (x0-mean)*rstd;
    g_a_ln[(size_t)row*CA + tid+256]  = (x1-mean)*rstd;
    __syncthreads();
    const float* sr = s + (size_t)row*CS;
    float y0 = sr[tid];
    float y1 = (tid < CS-256) ? sr[tid+256] : 0.f;
    sum = y0+y1; ss = y0*y0 + y1*y1;
    #pragma unroll
    for(int o=16;o;o>>=1){ sum += __shfl_xor_sync(0xffffffffu,sum,o); ss += __shfl_xor_sync(0xffffffffu,ss,o); }
    if((tid&31)==0){ rs[tid>>5]=sum; rs[8+(tid>>5)]=ss; }
    __syncthreads();
    if(tid==0){ float S=0,Q=0; for(int i=0;i<8;i++){S+=rs[i];Q+=rs[8+i];} rs[0]=S; rs[8]=Q; }
    __syncthreads();
    mean = rs[0]*(1.f/CS);
    var  = rs[8]*(1.f/CS) - mean*mean;
    rstd = rsqrtf(var + 1e-5f);
    g_s_ln[(size_t)row*CS + tid] = (y0-mean)*rstd*s_scale[tid];
    if(tid < CS-256)
        g_s_ln[(size_t)row*CS + tid+256] = (y1-mean)*rstd*s_scale[tid+256];
}

// -------------------- kernel 2: a_norm + glast (triple GEMM, f32x2) --------------------
__global__ __launch_bounds__(256) void anorm_kernel(
    const float* __restrict__ s_raw,
    const float* __restrict__ ada_w_s, const float* __restrict__ ada_b_s,
    const float* __restrict__ ada_w_nb,
    const float* __restrict__ w_last, const float* __restrict__ b_last)
{
    const int K = CS;
    __shared__ __align__(16) float As1[16][72];
    __shared__ __align__(16) float As2[16][72];
    __shared__ __align__(16) float Bs1[16][72];
    __shared__ __align__(16) float Bs2[16][72];
    __shared__ __align__(16) float Bs3[16][72];
    int tid = threadIdx.x;
    int tx = tid & 15, ty = tid >> 4;
    int m0 = blockIdx.y*64, n0 = blockIdx.x*64;
    U64 c1[4][2]={}, c2[4][2]={}, c3[4][2]={};
    for(int k0=0;k0<K;k0+=16){
        #pragma unroll
        for(int p=0;p<4;p++){
            int e = p*256 + tid;
            int mm = e>>4, kk = e&15;
            As1[kk][mm] = g_s_ln[(size_t)(m0+mm)*K + k0+kk];
            As2[kk][mm] = s_raw[(size_t)(m0+mm)*K + k0+kk];
            Bs1[kk][mm] = ada_w_s [(size_t)(n0+mm)*K + k0+kk];
            Bs2[kk][mm] = ada_w_nb[(size_t)(n0+mm)*K + k0+kk];
            Bs3[kk][mm] = w_last  [(size_t)(n0+mm)*K + k0+kk];
        }
        __syncthreads();
        #pragma unroll
        for(int kk=0;kk<16;kk++){
            float4 a1 = *(const float4*)&As1[kk][ty*4];
            float4 a2 = *(const float4*)&As2[kk][ty*4];
            ulonglong2 b1 = *(const ulonglong2*)&Bs1[kk][tx*4];
            ulonglong2 b2 = *(const ulonglong2*)&Bs2[kk][tx*4];
            ulonglong2 b3 = *(const ulonglong2*)&Bs3[kk][tx*4];
            U64 a1d[4], a2d[4];
            a1d[0]=pk2(a1.x,a1.x); a1d[1]=pk2(a1.y,a1.y); a1d[2]=pk2(a1.z,a1.z); a1d[3]=pk2(a1.w,a1.w);
            a2d[0]=pk2(a2.x,a2.x); a2d[1]=pk2(a2.y,a2.y); a2d[2]=pk2(a2.z,a2.z); a2d[3]=pk2(a2.w,a2.w);
            #pragma unroll
            for(int i=0;i<4;i++){
                fma2(c1[i][0],a1d[i],b1.x); fma2(c1[i][1],a1d[i],b1.y);
                fma2(c2[i][0],a1d[i],b2.x); fma2(c2[i][1],a1d[i],b2.y);
                fma2(c3[i][0],a2d[i],b3.x); fma2(c3[i][1],a2d[i],b3.y);
            }
        }
        __syncthreads();
    }
    #pragma unroll
    for(int i=0;i<4;i++){
        int m = m0 + ty*4 + i;
        #pragma unroll
        for(int jp=0;jp<2;jp++){
            float2 v1 = up2(c1[i][jp]), v2 = up2(c2[i][jp]), v3 = up2(c3[i][jp]);
            int n = n0 + tx*4 + jp*2;
            float sgA = sigm(v1.x + ada_b_s[n]);
            float sgB = sigm(v1.y + ada_b_s[n+1]);
            g_anorm[(size_t)m*CA + n]   = sgA * g_a_ln[(size_t)m*CA + n]   + v2.x;
            g_anorm[(size_t)m*CA + n+1] = sgB * g_a_ln[(size_t)m*CA + n+1] + v2.y;
            g_glast[(size_t)m*CA + n]   = sigm(v3.x + b_last[n]);
            g_glast[(size_t)m*CA + n+1] = sigm(v3.y + b_last[n+1]);
        }
    }
}

// -------------------- kernel 3: QKVG projections (tf32 tensor cores) ----------
// block tile 128(M) x 64(N), 8 warps = 4M x 2N, warp tile 32x32.
// mma.sync.aligned.m16n8k8.row.col.f32.tf32.tf32.f32
__global__ __launch_bounds__(256) void qkvg_kernel(
    const float* __restrict__ wq, const float* __restrict__ bq,
    const float* __restrict__ wk, const float* __restrict__ bk,
    const float* __restrict__ wv, const float* __restrict__ bv,
    const float* __restrict__ wg, const float* __restrict__ bg)
{
    __shared__ unsigned As[128][36];   // tf32 bits, pad 4
    __shared__ unsigned Bs[64][36];
    int tid = threadIdx.x;
    int lane = tid & 31, wid = tid >> 5;
    int warp_m = wid >> 1, warp_n = wid & 1;
    int m0 = blockIdx.y*128;
    int n0 = blockIdx.x*64;
    int which = n0 >> 9;
    int nn0 = n0 & 511;
    const float* W  = (which==0)?wq : (which==1)?wk : (which==2)?wv : wg;
    const float* Bv = (which==0)?bq : (which==1)?bk : (which==2)?bv : bg;

    float d[2][4][4];
    #pragma unroll
    for(int mt=0;mt<2;mt++)
    #pragma unroll
    for(int nt=0;nt<4;nt++)
    #pragma unroll
    for(int i=0;i<4;i++) d[mt][nt][i]=0.f;

    int r = lane >> 2, c = lane & 3;

    for(int k0=0;k0<CA;k0+=32){
        __syncthreads();
        #pragma unroll
        for(int p=0;p<4;p++){
            int idx = p*256 + tid;            // 1024 float4s of A
            int mm = idx >> 3, kf = idx & 7;
            float4 v = *(const float4*)&g_anorm[(size_t)(m0+mm)*CA + k0 + kf*4];
            *(uint4*)&As[mm][kf*4] = make_uint4(f2tf(v.x),f2tf(v.y),f2tf(v.z),f2tf(v.w));
        }
        #pragma unroll
        for(int p=0;p<2;p++){
            int idx = p*256 + tid;            // 512 float4s of B
            int nn = idx >> 3, kf = idx & 7;
            float4 v = *(const float4*)&W[(size_t)(nn0+nn)*CA + k0 + kf*4];
            *(uint4*)&Bs[nn][kf*4] = make_uint4(f2tf(v.x),f2tf(v.y),f2tf(v.z),f2tf(v.w));
        }
        __syncthreads();

        #pragma unroll
        for(int kc=0;kc<32;kc+=8){
            unsigned a[2][4], b2[4][2];
            #pragma unroll
            for(int mt=0;mt<2;mt++){
                int rb = warp_m*32 + mt*16;
                a[mt][0] = As[rb+r  ][kc+c  ];
                a[mt][1] = As[rb+r+8][kc+c  ];
                a[mt][2] = As[rb+r  ][kc+c+4];
                a[mt][3] = As[rb+r+8][kc+c+4];
            }
            #pragma unroll
            for(int nt=0;nt<4;nt++){
                int nb = warp_n*32 + nt*8;
                b2[nt][0] = Bs[nb+r][kc+c  ];
                b2[nt][1] = Bs[nb+r][kc+c+4];
            }
            #pragma unroll
            for(int mt=0;mt<2;mt++)
            #pragma unroll
            for(int nt=0;nt<4;nt++){
                asm volatile(
                    "mma.sync.aligned.m16n8k8.row.col.f32.tf32.tf32.f32 "
                    "{%0,%1,%2,%3}, {%4,%5,%6,%7}, {%8,%9}, {%0,%1,%2,%3};"
                    : "+f"(d[mt][nt][0]), "+f"(d[mt][nt][1]),
                      "+f"(d[mt][nt][2]), "+f"(d[mt][nt][3])
                    : "r"(a[mt][0]),"r"(a[mt][1]),"r"(a[mt][2]),"r"(a[mt][3]),
                      "r"(b2[nt][0]),"r"(b2[nt][1]));
            }
        }
    }

    float* dst = (which==0)?g_q : (which==1)?g_k : g_v;
    int c2 = (lane & 3)*2;
    #pragma unroll
    for(int mt=0;mt<2;mt++){
        #pragma unroll
        for(int nt=0;nt<4;nt++){
            int nn = nn0 + warp_n*32 + nt*8 + c2;
            float bb0 = Bv[nn], bb1 = Bv[nn+1];
            #pragma unroll
            for(int rr=0;rr<2;rr++){
                int m = m0 + warp_m*32 + mt*16 + r + rr*8;
                float v0 = d[mt][nt][rr*2+0] + bb0;
                float v1 = d[mt][nt][rr*2+1] + bb1;
                if(which < 3){
                    int hh = nn>>5, dd2 = nn&31;
                    int bbx = m>>10, ll = m&1023;
                    *(float2*)&dst[(((size_t)(bbx*HH+hh))*LL + ll)*DD + dd2] = make_float2(v0,v1);
                } else {
                    *(float2*)&g_g[(size_t)m*CA + nn] = make_float2(v0,v1);
                }
            }
        }
    }
}

// -------------------- kernel 4: pair bias (mask-skip, no dead stores) ----------
__global__ __launch_bounds__(256) void bias_kernel(
    const float* __restrict__ z, const float* __restrict__ z_scale,
    const float* __restrict__ wz, const int* __restrict__ mask)
{
    __shared__ __align__(16) U64 wzs2[HH][CZ/2];
    __shared__ float wsum[HH];
    int tid = threadIdx.x;
    for(int e=tid;e<HH*(CZ/2);e+=256){
        int h = e>>5, c2 = e&31;
        float w0 = wz[h*CZ + 2*c2    ]*z_scale[2*c2    ];
        float w1 = wz[h*CZ + 2*c2 + 1]*z_scale[2*c2 + 1];
        wzs2[h][c2] = pk2(w0,w1);
    }
    __syncthreads();
    if(tid < HH){
        float S=0.f;
        for(int c2=0;c2<CZ/2;c2++){ float2 t=up2(wzs2[tid][c2]); S += t.x + t.y; }
        wsum[tid]=S;
    }
    __syncthreads();

    size_t t0 = (size_t)blockIdx.x*256 + tid;
    int b_ = (int)(t0>>20), q_ = (int)((t0>>10)&1023), k_ = (int)(t0&1023);

    bool active = (mask[b_*LL + q_] != 0) && (mask[b_*LL + k_] != 0);
    if(!active) return;

    size_t ob = (((size_t)(b_*HH))*LL + q_)*LL + k_;
    const float4* zp = (const float4*)(z + t0*CZ);
    U64 acc[HH];
    #pragma unroll
    for(int h=0;h<HH;h++) acc[h]=0ull;
    U64 sum=0ull, ssq=0ull;
    const U64 one2 = pk2(1.f,1.f);

    #pragma unroll
    for(int cs=0;cs<16;cs++){
        float4 a = zp[cs];
        U64 p01 = pk2(a.x,a.y);
        U64 p23 = pk2(a.z,a.w);
        fma2(sum,p01,one2); fma2(sum,p23,one2);
        fma2(ssq,p01,p01);  fma2(ssq,p23,p23);
        #pragma unroll
        for(int h=0;h<HH;h++){
            ulonglong2 w = *(const ulonglong2*)&wzs2[h][cs*2];
            fma2(acc[h],p01,w.x);
            fma2(acc[h],p23,w.y);
        }
    }
    float2 s2=up2(sum), q2=up2(ssq);
    float mean = (s2.x+s2.y)*(1.f/CZ);
    float var  = (q2.x+q2.y)*(1.f/CZ) - mean*mean;
    float rstd = rsqrtf(var + 1e-5f);

    #pragma unroll
    for(int h=0;h<HH;h++){
        float2 d = up2(acc[h]);
        float v = rstd*((d.x+d.y) - mean*wsum[h]);
        g_biash[ob + (size_t)h*LL*LL] = __float2half(v);
    }
}

// -------------------- kernel 5: attention (round-11: key-skip, staged bias) ------
__global__ __launch_bounds__(128) void attn_kernel(const int* __restrict__ mask)
{
    __shared__ __align__(16) float Ks[64*32];
    __shared__ __align__(16) float Vs[64*32];
    __shared__ __align__(16) __half bsh[64][80];
    __shared__ float mk[64];

    int tid = threadIdx.x;          // 128
    int b = blockIdx.z, h = blockIdx.y;
    int q0 = blockIdx.x*64;
    int row = tid >> 1;             // 0..63
    int half = tid & 1;             // which 16-d half

    const float* qp = g_q + (((size_t)(b*HH+h))*LL + q0+row)*DD + half*16;
    U64 qr2[8];
    #pragma unroll
    for(int i=0;i<4;i++){
        float4 t4 = ((const float4*)qp)[i];
        qr2[i*2]   = pk2(t4.x*SCALE, t4.y*SCALE);
        qr2[i*2+1] = pk2(t4.z*SCALE, t4.w*SCALE);
    }
    U64 O2[8];
    #pragma unroll
    for(int i=0;i<8;i++) O2[i]=0ull;
    float lrun = 0.f;

    const float* Kbase = g_k + ((size_t)(b*HH+h))*LL*DD;
    const float* Vbase = g_v + ((size_t)(b*HH+h))*LL*DD;
    const __half* bbase = g_biash + (((size_t)(b*HH+h))*LL + q0)*LL;

    for(int kt=0; kt<LL; kt+=64){
        __syncthreads();
        #pragma unroll
        for(int p=0;p<4;p++){
            int f = p*128 + tid;  // 512 float4s
            ((float4*)Ks)[f] = ((const float4*)(Kbase + (size_t)kt*DD))[f];
            ((float4*)Vs)[f] = ((const float4*)(Vbase + (size_t)kt*DD))[f];
        }
        #pragma unroll
        for(int p=0;p<4;p++){
            int c = p*128 + tid;   // 512 chunks of 8 halves
            int r = c>>3, part = c&7;
            *(float4*)&bsh[r][part*8] = ((const float4*)(bbase + (size_t)r*LL + kt))[part];
        }
        if(tid < 64) mk[tid] = mask[b*LL + kt + tid] ? 0.f : -10000.f;
        __syncthreads();

        for(int j0=0;j0<64;j0+=4){
            const __half2* bp = (const __half2*)&bsh[row][j0];
            float2 b01 = __half22float2(bp[0]);
            float2 b23 = __half22float2(bp[1]);
            float bb4[4] = {b01.x, b01.y, b23.x, b23.y};
            #pragma unroll
            for(int jj=0;jj<4;jj++){
                int j = j0 + jj;
                if(mk[j] == 0.f){   // uniform across block: skip masked keys (exp==0)
                    const ulonglong2* kp = (const ulonglong2*)&Ks[j*32 + half*16];
                    U64 sacc = 0ull;
                    #pragma unroll
                    for(int i=0;i<4;i++){
                        ulonglong2 kv = kp[i];
                        fma2(sacc, qr2[i*2],   kv.x);
                        fma2(sacc, qr2[i*2+1], kv.y);
                    }
                    float2 sp = up2(sacc);
                    float part = sp.x + sp.y;
                    float tot = part + __shfl_xor_sync(0xffffffffu, part, 1);
                    float s_ = tot + bb4[jj];
                    float p_ = __expf(s_);
                    lrun += p_;
                    U64 pp = pk2(p_, p_);
                    const ulonglong2* vp = (const ulonglong2*)&Vs[j*32 + half*16];
                    #pragma unroll
                    for(int i=0;i<4;i++){
                        ulonglong2 vv = vp[i];
                        fma2(O2[i*2],   pp, vv.x);
                        fma2(O2[i*2+1], pp, vv.y);
                    }
                }
            }
        }
    }
    float inv = 1.f/fmaxf(lrun, 1e-20f);
    float* dst = g_ao + ((size_t)(b*LL + q0+row))*CA + h*DD + half*16;
    #pragma unroll
    for(int i=0;i<4;i++){
        float2 v0 = up2(O2[i*2]), v1 = up2(O2[i*2+1]);
        ((float4*)dst)[i] = make_float4(v0.x*inv, v0.y*inv, v1.x*inv, v1.y*inv);
    }
}

// -------------------- kernel 6: output GEMM (f32x2) --------------------
__global__ __launch_bounds__(256) void out_kernel(
    const float* __restrict__ wo, const float* __restrict__ bo,
    const int* __restrict__ mask, float* __restrict__ out)
{
    const int K = CA;
    __shared__ __align__(16) float As[16][72];
    __shared__ __align__(16) float Bs[16][72];
    int tid = threadIdx.x;
    int tx = tid & 15, ty = tid >> 4;
    int m0 = blockIdx.y*64, n0 = blockIdx.x*64;
    U64 c[4][2]={};
    for(int k0=0;k0<K;k0+=16){
        #pragma unroll
        for(int p=0;p<4;p++){
            int e = p*256 + tid;
            int mm = e>>4, kk = e&15;
            size_t ai = (size_t)(m0+mm)*K + k0+kk;
            As[kk][mm] = sigm(g_g[ai]) * g_ao[ai];
            Bs[kk][mm] = wo[(size_t)(n0+mm)*K + k0+kk];
        }
        __syncthreads();
        #pragma unroll
        for(int kk=0;kk<16;kk++){
            float4 a4 = *(const float4*)&As[kk][ty*4];
            ulonglong2 bu = *(const ulonglong2*)&Bs[kk][tx*4];
            U64 ad[4];
            ad[0]=pk2(a4.x,a4.x); ad[1]=pk2(a4.y,a4.y); ad[2]=pk2(a4.z,a4.z); ad[3]=pk2(a4.w,a4.w);
            #pragma unroll
            for(int i=0;i<4;i++){
                fma2(c[i][0],ad[i],bu.x);
                fma2(c[i][1],ad[i],bu.y);
            }
        }
        __syncthreads();
    }
    #pragma unroll
    for(int i=0;i<4;i++){
        int m = m0 + ty*4 + i;
        float mq = mask[m] ? 1.f : 0.f;
        #pragma unroll
        for(int jp=0;jp<2;jp++){
            float2 v = up2(c[i][jp]);
            int n = n0 + tx*4 + jp*2;
            out[(size_t)m*CA + n]   = (v.x + bo[n])   * g_glast[(size_t)m*CA + n]   * mq;
            out[(size_t)m*CA + n+1] = (v.y + bo[n+1]) * g_glast[(size_t)m*CA + n+1] * mq;
        }
    }
}

// -------------------- launch (fork-join: bias overlaps ln/anorm/qkvg) ----------
extern "C" void kernel_launch(void* const* d_in, const int* in_sizes, int n_in,
                              void* d_out, int out_size)
{
    const float* a          = (const float*)d_in[0];
    const float* s          = (const float*)d_in[1];
    const float* z          = (const float*)d_in[2];
    const float* ln_s_scale = (const float*)d_in[3];
    const float* ada_w_s    = (const float*)d_in[4];
    const float* ada_b_s    = (const float*)d_in[5];
    const float* ada_w_nb   = (const float*)d_in[6];
    const float* wq = (const float*)d_in[7];  const float* bq = (const float*)d_in[8];
    const float* wk = (const float*)d_in[9];  const float* bk = (const float*)d_in[10];
    const float* wv = (const float*)d_in[11]; const float* bv = (const float*)d_in[12];
    const float* wg = (const float*)d_in[13]; const float* bg = (const float*)d_in[14];
    const float* wo = (const float*)d_in[15]; const float* bo = (const float*)d_in[16];
    const float* ln_z_scale = (const float*)d_in[17];
    const float* wz         = (const float*)d_in[18];
    const float* w_last     = (const float*)d_in[19];
    const float* b_last     = (const float*)d_in[20];
    const int*   mask       = (const int*)d_in[21];
    float* out = (float*)d_out;

    static cudaStream_t s_bias = 0;
    static cudaEvent_t ev_fork = 0, ev_join = 0;
    if(!s_bias){
        cudaStreamCreateWithFlags(&s_bias, cudaStreamNonBlocking);
        cudaEventCreateWithFlags(&ev_fork, cudaEventDisableTiming);
        cudaEventCreateWithFlags(&ev_join, cudaEventDisableTiming);
    }

    // fork: bias branch (depends only on z, ln_z_scale, wz, mask)
    cudaEventRecord(ev_fork, 0);
    cudaStreamWaitEvent(s_bias, ev_fork, 0);
    bias_kernel<<<(BB*LL*LL)/256, 256, 0, s_bias>>>(z, ln_z_scale, wz, mask);
    cudaEventRecord(ev_join, s_bias);

    // main branch
    ln_kernel<<<MM, 256>>>(a, s, ln_s_scale);
    anorm_kernel<<<dim3(CA/64, MM/64), 256>>>(s, ada_w_s, ada_b_s, ada_w_nb, w_last, b_last);
    qkvg_kernel<<<dim3(2048/64, MM/128), 256>>>(wq,bq, wk,bk, wv,bv, wg,bg);

    // join: attention needs both bias and q/k/v
    cudaStreamWaitEvent(0, ev_join, 0);
    attn_kernel<<<dim3(LL/64, HH, BB), 128>>>(mask);
    out_kernel<<<dim3(CA/64, MM/64), 256>>>(wo, bo, mask, out);
}